// round 7
// baseline (speedup 1.0000x reference)
#include <cuda_runtime.h>
#include <cuda_fp16.h>
#include <cstdint>

// ---------------------------------------------------------------------------
// GumbelSoftmaxModule4 v7: fp16 m16n8k16, GEMM1+exp+GEMM2 interleaved per
// 64-code chunk (8 fat iterations; loads get 2x window, half the barriers).
// ---------------------------------------------------------------------------

namespace {
constexpr int KQ = 512, NG = 4, SDQ = 128, BQ = 16, TQ = 2048;
constexpr int NTOK = BQ * TQ;            // 32768
constexpr int TM   = 64;                 // tokens per CTA
constexpr int NTHR = 512;                // 16 warps
constexpr int PSW  = 272;                // sP row stride (uint32 words)
constexpr int SXS  = 68;                 // X / quant stage row stride (f32)
constexpr int W1B  = 320;                // GEMM1 W row bytes (128 halves used)
constexpr int W2B  = 192;                // GEMM2 Wt row bytes (64 halves used)
constexpr int WTOFF = 20480;             // wt offset inside a combined buffer
constexpr int WBUF  = 45056;             // combined (w1 + wt) chunk buffer
constexpr int OFF_P   = 0;                         // 69632 B (sX overlays)
constexpr int OFF_WB  = 69632;                     // 2 x 45056
constexpr int OFF_CSQ = OFF_WB + 2 * WBUF;         // 159744: 512 f32
constexpr int OFF_RS  = OFF_CSQ + 2048;            // 64 f32
constexpr int OFF_RI  = OFF_RS + 256;              // 64 f32
constexpr int SMEM_BYTES = OFF_RI + 256;           // 162304
constexpr int QUANT_ELEMS = BQ * 512 * TQ;
}

__device__ float g_csq[NG * KQ];
__device__ float g_avg[NG * KQ];
__device__ __align__(16) uint32_t g_w1[NG * KQ * 64];    // [g][code][pos32 d pairs]
__device__ __align__(16) uint32_t g_wt[NG * SDQ * 256];  // [g][d][pos32 code pairs]

// ------------------------------ helpers ------------------------------------
__device__ __forceinline__ int inv16(int o) {
    return (((o >> 1) & 1) << 4) | ((o & 1) << 3) | (((o >> 2) & 3) << 1);
}
__device__ __forceinline__ uint32_t pk(float lo, float hi) {
    __half2 h = __floats2half2_rn(lo, hi);
    return *reinterpret_cast<uint32_t*>(&h);
}
__device__ __forceinline__ float fexp(float x) {   // FMA-only exp
    float y = x * 1.4426950408889634f;
    float n = rintf(y);
    float f = y - n;
    float p = 1.3333558146428443e-3f;
    p = fmaf(p, f, 9.618129107628477e-3f);
    p = fmaf(p, f, 5.550410866482158e-2f);
    p = fmaf(p, f, 2.402265069591007e-1f);
    p = fmaf(p, f, 6.931471805599453e-1f);
    p = fmaf(p, f, 1.0f);
    return p * __int_as_float(((int)n + 127) << 23);
}
__device__ __forceinline__ void mma_f16(float* c,
                                        uint32_t a0, uint32_t a1, uint32_t a2, uint32_t a3,
                                        uint32_t b0, uint32_t b1) {
    asm volatile(
        "mma.sync.aligned.m16n8k16.row.col.f32.f16.f16.f32 "
        "{%0,%1,%2,%3}, {%4,%5,%6,%7}, {%8,%9}, {%0,%1,%2,%3};\n"
        : "+f"(c[0]), "+f"(c[1]), "+f"(c[2]), "+f"(c[3])
        : "r"(a0), "r"(a1), "r"(a2), "r"(a3), "r"(b0), "r"(b1));
}
__device__ __forceinline__ uint32_t smem_u32(const void* p) {
    uint32_t a;
    asm("{ .reg .u64 t; cvta.to.shared.u64 t, %1; cvt.u32.u64 %0, t; }"
        : "=r"(a) : "l"(p));
    return a;
}
__device__ __forceinline__ void cpa16(uint32_t dst, const void* src) {
    asm volatile("cp.async.cg.shared.global [%0], [%1], 16;" :: "r"(dst), "l"(src));
}
#define CP_COMMIT() asm volatile("cp.async.commit_group;" ::: "memory")
#define CP_WAIT0()  asm volatile("cp.async.wait_group 0;" ::: "memory")

__device__ __forceinline__ const float* pick_w(const float* w0, const float* w1,
                                               const float* w2, const float* w3, int g) {
    return (g == 0) ? w0 : ((g == 1) ? w1 : ((g == 2) ? w2 : w3));
}

// ---------------------------------------------------------------------------
// prep: 64 blocks = (g, kt, quarter). csq + g_w1 + g_wt + zero g_avg.
// ---------------------------------------------------------------------------
__global__ void gsm4_prep_kernel(const float* __restrict__ w0, const float* __restrict__ w1,
                                 const float* __restrict__ w2, const float* __restrict__ w3) {
    extern __shared__ float sw[];                  // [128][132] raw f32 tile
    const int bx = blockIdx.x;
    const int g  = bx >> 4;
    const int kt = (bx >> 2) & 3;
    const int q  = bx & 3;
    const int tid = threadIdx.x;
    const float* W = pick_w(w0, w1, w2, w3, g) + (size_t)kt * 128 * SDQ;

    #pragma unroll
    for (int j = 0; j < 16; j++) {
        int i = tid + 256 * j;
        int k = i >> 5, dq = (i & 31) * 4;
        *(float4*)(sw + k * 132 + dq) = *(const float4*)(W + (size_t)k * SDQ + dq);
    }
    if (bx == 0) {
        #pragma unroll
        for (int j = 0; j < 8; j++) g_avg[tid + 256 * j] = 0.f;
    }
    __syncthreads();

    if (tid < 32) {
        int k = 32 * q + tid;
        const float* r = sw + k * 132;
        float s0 = 0.f, s1 = 0.f, s2 = 0.f, s3 = 0.f;
        #pragma unroll 8
        for (int d = 0; d < SDQ; d += 4) {
            s0 = fmaf(r[d], r[d], s0);
            s1 = fmaf(r[d + 1], r[d + 1], s1);
            s2 = fmaf(r[d + 2], r[d + 2], s2);
            s3 = fmaf(r[d + 3], r[d + 3], s3);
        }
        g_csq[g * KQ + kt * 128 + k] = (s0 + s1) + (s2 + s3);
    }

    #pragma unroll
    for (int j = 0; j < 8; j++) {
        int idx = tid + 256 * j;
        int k = 32 * q + (idx >> 6);
        int o = idx & 63;
        int d0 = (o >> 4) * 32 + inv16(o & 15);
        g_w1[((size_t)(g * KQ + kt * 128 + k)) * 64 + o] =
            pk(sw[k * 132 + d0], sw[k * 132 + d0 + 1]);
    }
    #pragma unroll
    for (int j = 0; j < 8; j++) {
        int idx = tid + 256 * j;
        int d = 32 * q + (idx >> 6);
        int o = idx & 63;
        int lc = (o >> 4) * 32 + inv16(o & 15);
        g_wt[((size_t)(g * SDQ + d)) * 256 + kt * 64 + o] =
            pk(sw[lc * 132 + d], sw[(lc + 1) * 132 + d]);
    }
}

// ---------------------------------------------------------------------------
// fused main kernel: CTA = (group g, 64-token tile), 512 threads / 16 warps
// ---------------------------------------------------------------------------
__global__ __launch_bounds__(NTHR, 1)
void gsm4_fused_kernel(const float* __restrict__ x,
                       const float* __restrict__ gum,
                       float* __restrict__ out) {
    extern __shared__ char smc[];
    const uint32_t smb = smem_u32(smc);
    const int g  = blockIdx.y;
    const int n0 = blockIdx.x * TM;
    const int b  = n0 / TQ;
    const int t0 = n0 % TQ;

    const int tid  = threadIdx.x;
    const int wid  = tid >> 5;
    const int lane = tid & 31;
    const int lg   = lane >> 2;
    const int lt   = lane & 3;
    const int wm   = wid >> 2;
    const int wq   = wid & 3;
    const int m0   = wm * 16;

    uint32_t* sP   = (uint32_t*)(smc + OFF_P);
    float* sX      = (float*)(smc + OFF_P);        // overlay
    float* sCsq    = (float*)(smc + OFF_CSQ);
    float* sRs     = (float*)(smc + OFF_RS);
    float* sRinv   = (float*)(smc + OFF_RI);

    // combined W chunk loader: w1[c] (64x320B) + wt[c] (128x192B) in one group
    auto cp_chunk = [&](int c, int buf) {
        uint32_t dst = smb + OFF_WB + buf * WBUF;
        const char* s1 = (const char*)g_w1 + ((size_t)(g * KQ + c * 64)) * 256;
        #pragma unroll
        for (int j = 0; j < 2; j++) {
            int i = tid + NTHR * j;
            int r = i >> 4, o = i & 15;
            cpa16(dst + r * W1B + o * 16, s1 + (size_t)r * 256 + o * 16);
        }
        const char* s2 = (const char*)g_wt + ((size_t)(g * SDQ)) * 1024 + c * 128;
        uint32_t dwt = dst + WTOFF;
        #pragma unroll
        for (int j = 0; j < 2; j++) {
            int i = tid + NTHR * j;
            int r = i >> 3, o = i & 7;
            cpa16(dwt + r * W2B + o * 16, s2 + (size_t)r * 1024 + o * 16);
        }
    };

    // prologue --------------------------------------------------------------
    cp_chunk(0, 0);
    CP_COMMIT();

    sCsq[tid] = 0.5f * g_csq[g * KQ + tid];
    if (tid < 64) sRs[tid] = 0.f;

    {
        const float* xb = x + ((size_t)(b * 512 + g * SDQ)) * TQ + t0;
        #pragma unroll
        for (int j = 0; j < 4; j++) {
            int i = tid + NTHR * j;
            int d = i >> 4, mq = (i & 15) * 4;
            *(float4*)(sX + d * SXS + mq) = *(const float4*)(xb + (size_t)d * TQ + mq);
        }
    }
    __syncthreads();

    // A fragments (GEMM1): 8 k16-steps x 4 half2 regs -----------------------
    uint32_t af[8][4];
    #pragma unroll
    for (int s = 0; s < 8; s++) {
        int dbs = 16 * s + 2 * lt;
        af[s][0] = pk(sX[dbs * SXS + m0 + lg],           sX[(dbs + 1) * SXS + m0 + lg]);
        af[s][1] = pk(sX[dbs * SXS + m0 + lg + 8],       sX[(dbs + 1) * SXS + m0 + lg + 8]);
        af[s][2] = pk(sX[(dbs + 8) * SXS + m0 + lg],     sX[(dbs + 9) * SXS + m0 + lg]);
        af[s][3] = pk(sX[(dbs + 8) * SXS + m0 + lg + 8], sX[(dbs + 9) * SXS + m0 + lg + 8]);
    }
    __syncthreads();                                // sX dead -> sP region

    // gumbel prefetch (one chunk ahead) -------------------------------------
    const float* gmr = gum + ((size_t)g * NTOK + n0 + m0 + lg) * KQ + wq * 16 + 2 * lt;
    float2 gb[2][4];
    {
        const float* p0 = gmr;
        gb[0][0] = *(const float2*)(p0);
        gb[0][1] = *(const float2*)(p0 + 8);
        gb[0][2] = *(const float2*)(p0 + 8 * KQ);
        gb[0][3] = *(const float2*)(p0 + 8 * KQ + 8);
    }

    // ---------------- fused loop: 8 chunks of 64 codes ---------------------
    float rs0 = 0.f, rs1 = 0.f;
    float qa[4][4];
    #pragma unroll
    for (int t = 0; t < 4; t++)
        #pragma unroll
        for (int e = 0; e < 4; e++) qa[t][e] = 0.f;

    for (int c = 0; c < 8; c++) {
        CP_WAIT0();
        __syncthreads();
        if (c < 7) {
            cp_chunk(c + 1, (c + 1) & 1);
            CP_COMMIT();
            const float* p0 = gmr + (c + 1) * 64;
            gb[(c + 1) & 1][0] = *(const float2*)(p0);
            gb[(c + 1) & 1][1] = *(const float2*)(p0 + 8);
            gb[(c + 1) & 1][2] = *(const float2*)(p0 + 8 * KQ);
            gb[(c + 1) & 1][3] = *(const float2*)(p0 + 8 * KQ + 8);
        }
        const char* wb = smc + OFF_WB + (c & 1) * WBUF;

        // GEMM1 chunk c ------------------------------------------------------
        float acc[2][4] = {{0.f, 0.f, 0.f, 0.f}, {0.f, 0.f, 0.f, 0.f}};
        #pragma unroll
        for (int kg = 0; kg < 4; kg++) {
            #pragma unroll
            for (int t = 0; t < 2; t++) {
                uint4 B = *(const uint4*)(wb + (wq * 16 + t * 8 + lg) * W1B + kg * 64 + lt * 16);
                mma_f16(acc[t], af[2 * kg][0], af[2 * kg][1], af[2 * kg][2], af[2 * kg][3], B.x, B.y);
                mma_f16(acc[t], af[2 * kg + 1][0], af[2 * kg + 1][1], af[2 * kg + 1][2], af[2 * kg + 1][3], B.z, B.w);
            }
        }
        // fused exp epilogue -> sP chunk c ------------------------------------
        {
            const int colb = c * 64 + wq * 16 + 2 * lt;
            float2 cs0 = *(const float2*)(sCsq + colb);
            float2 cs1 = *(const float2*)(sCsq + colb + 8);
            const float2* gv = gb[c & 1];
            float p00 = fexp(acc[0][0] - cs0.x + 0.5f * gv[0].x);
            float p01 = fexp(acc[0][1] - cs0.y + 0.5f * gv[0].y);
            float p10 = fexp(acc[1][0] - cs1.x + 0.5f * gv[1].x);
            float p11 = fexp(acc[1][1] - cs1.y + 0.5f * gv[1].y);
            float p20 = fexp(acc[0][2] - cs0.x + 0.5f * gv[2].x);
            float p21 = fexp(acc[0][3] - cs0.y + 0.5f * gv[2].y);
            float p30 = fexp(acc[1][2] - cs1.x + 0.5f * gv[3].x);
            float p31 = fexp(acc[1][3] - cs1.y + 0.5f * gv[3].y);
            rs0 += (p00 + p01) + (p10 + p11);
            rs1 += (p20 + p21) + (p30 + p31);
            const int wbase = (m0 + lg) * PSW + c * 32 + (wq >> 1) * 16 + 4 * lt + 2 * (wq & 1);
            *(uint2*)(sP + wbase)           = make_uint2(pk(p00, p01), pk(p10, p11));
            *(uint2*)(sP + wbase + 8 * PSW) = make_uint2(pk(p20, p21), pk(p30, p31));
        }
        __syncthreads();

        // GEMM2 chunk c -------------------------------------------------------
        const char* wt = wb + WTOFF;
        #pragma unroll
        for (int g2 = 0; g2 < 2; g2++) {
            uint4 U = *(const uint4*)(sP + (m0 + lg) * PSW + (c * 2 + g2) * 16 + 4 * lt);
            uint4 V = *(const uint4*)(sP + (m0 + lg + 8) * PSW + (c * 2 + g2) * 16 + 4 * lt);
            #pragma unroll
            for (int t = 0; t < 4; t++) {
                uint4 B = *(const uint4*)(wt + (wq * 32 + t * 8 + lg) * W2B + g2 * 64 + lt * 16);
                mma_f16(qa[t], U.x, V.x, U.y, V.y, B.x, B.y);
                mma_f16(qa[t], U.z, V.z, U.w, V.w, B.z, B.w);
            }
        }
    }

    // rowsums ---------------------------------------------------------------
    rs0 += __shfl_xor_sync(0xffffffffu, rs0, 1);
    rs0 += __shfl_xor_sync(0xffffffffu, rs0, 2);
    rs1 += __shfl_xor_sync(0xffffffffu, rs1, 1);
    rs1 += __shfl_xor_sync(0xffffffffu, rs1, 2);
    if (lt == 0) {
        atomicAdd(&sRs[m0 + lg], rs0);
        atomicAdd(&sRs[m0 + lg + 8], rs1);
    }
    __syncthreads();
    if (tid < 64) sRinv[tid] = 1.0f / sRs[tid];
    __syncthreads();

    // avg_probs -------------------------------------------------------------
    {
        int w = tid >> 1;
        int rb = (tid & 1) * 32;
        float s0 = 0.f, s1 = 0.f;
        #pragma unroll 8
        for (int r = 0; r < 32; r++) {
            uint32_t u = sP[(rb + r) * PSW + w];
            __half2 h = *reinterpret_cast<__half2*>(&u);
            float2 f = __half22float2(h);
            float ri = sRinv[rb + r];
            s0 = fmaf(f.x, ri, s0);
            s1 = fmaf(f.y, ri, s1);
        }
        s0 += __shfl_xor_sync(0xffffffffu, s0, 1);
        s1 += __shfl_xor_sync(0xffffffffu, s1, 1);
        if (!(tid & 1)) {
            int o = w & 15;
            int k0 = (w >> 4) * 32 + ((((o >> 1) & 1) << 4) | ((o & 1) << 3) | (((o >> 2) & 3) << 1));
            atomicAdd(&g_avg[g * KQ + k0], s0);
            atomicAdd(&g_avg[g * KQ + k0 + 1], s1);
        }
    }
    __syncthreads();                                // W buffers free for staging

    // epilogue: normalize, transpose via smem, coalesced STG.128 ------------
    {
        float* stage = (float*)(smc + OFF_WB);      // [128 d][SXS]
        const float r1v = sRinv[m0 + lg];
        const float r2v = sRinv[m0 + lg + 8];
        #pragma unroll
        for (int t = 0; t < 4; t++) {
            int d = wq * 32 + t * 8 + 2 * lt;
            stage[d * SXS + m0 + lg]           = qa[t][0] * r1v;
            stage[(d + 1) * SXS + m0 + lg]     = qa[t][1] * r1v;
            stage[d * SXS + m0 + lg + 8]       = qa[t][2] * r2v;
            stage[(d + 1) * SXS + m0 + lg + 8] = qa[t][3] * r2v;
        }
        __syncthreads();
        #pragma unroll
        for (int j = 0; j < 4; j++) {
            int i = tid + NTHR * j;
            int d = i >> 4, mq = (i & 15) * 4;
            float4 v = *(const float4*)(stage + d * SXS + mq);
            *(float4*)(out + ((size_t)(b * 512 + g * SDQ + d)) * TQ + t0 + mq) = v;
        }
    }
}

// ---------------------------------------------------------------------------
// perplexity
// ---------------------------------------------------------------------------
__global__ void gsm4_perp_kernel(float* __restrict__ out) {
    __shared__ float se[NG];
    int w = threadIdx.x >> 5;
    int lane = threadIdx.x & 31;
    float acc = 0.f;
    for (int k = lane; k < KQ; k += 32) {
        float a = g_avg[w * KQ + k] * (1.0f / (float)NTOK);
        acc += a * logf(a + 1e-10f);
    }
    #pragma unroll
    for (int o = 16; o; o >>= 1) acc += __shfl_xor_sync(0xffffffffu, acc, o);
    if (lane == 0) se[w] = acc;
    __syncthreads();
    if (threadIdx.x == 0) {
        float p = 0.f;
        #pragma unroll
        for (int gg = 0; gg < NG; gg++) p += expf(-se[gg]);
        out[QUANT_ELEMS] = p;
    }
}

// ---------------------------------------------------------------------------
extern "C" void kernel_launch(void* const* d_in, const int* in_sizes, int n_in,
                              void* d_out, int out_size) {
    const float* x   = (const float*)d_in[0];
    const float* w0  = (const float*)d_in[1];
    const float* w1  = (const float*)d_in[2];
    const float* w2  = (const float*)d_in[3];
    const float* w3  = (const float*)d_in[4];
    const float* gum = (const float*)d_in[5];
    float* out = (float*)d_out;

    cudaFuncSetAttribute(gsm4_prep_kernel,
                         cudaFuncAttributeMaxDynamicSharedMemorySize, 128 * 132 * 4);
    cudaFuncSetAttribute(gsm4_fused_kernel,
                         cudaFuncAttributeMaxDynamicSharedMemorySize, SMEM_BYTES);

    gsm4_prep_kernel<<<64, 256, 128 * 132 * 4>>>(w0, w1, w2, w3);

    dim3 grid(NTOK / TM, NG);
    gsm4_fused_kernel<<<grid, NTHR, SMEM_BYTES>>>(x, gum, out);

    if (out_size > QUANT_ELEMS) {
        gsm4_perp_kernel<<<1, NG * 32>>>(out);
    }
}

// round 8
// speedup vs baseline: 1.2448x; 1.2448x over previous
#include <cuda_runtime.h>
#include <cuda_fp16.h>
#include <cstdint>

// ---------------------------------------------------------------------------
// GumbelSoftmaxModule4 v8: fp16 m16n8k16, TM=128 tokens/CTA, 3-stage cp.async
// pipeline, unified 16-chunk loop (8 GEMM1+exp, 8 GEMM2), STS.128 prob stores.
// ---------------------------------------------------------------------------

namespace {
constexpr int KQ = 512, NG = 4, SDQ = 128, BQ = 16, TQ = 2048;
constexpr int NTOK = BQ * TQ;            // 32768
constexpr int TM   = 128;                // tokens per CTA
constexpr int NTHR = 512;                // 16 warps
constexpr int PSW  = 272;                // sP row stride (uint32 words), %32=16
constexpr int SXS  = 132;                // X / out stage row stride (f32), %32=4
constexpr int W1B  = 320;                // GEMM1 W row bytes (256 used)
constexpr int W2B  = 192;                // GEMM2 Wt row bytes (128 used)
constexpr int WBUF = 24576;              // per pipeline-stage buffer
constexpr int OFF_P   = 0;                          // sP: 128*272*4 = 139264
constexpr int OFF_WB  = 139264;                     // 3 x 24576
constexpr int OFF_CSQ = OFF_WB + 3 * WBUF;          // 212992: 512 f32
constexpr int OFF_RS  = OFF_CSQ + 2048;             // 128 f32
constexpr int OFF_RI  = OFF_RS + 512;               // 128 f32
constexpr int SMEM_BYTES = OFF_RI + 512;            // 216064
constexpr int QUANT_ELEMS = BQ * 512 * TQ;
}

__device__ float g_csq[NG * KQ];
__device__ float g_avg[NG * KQ];
__device__ __align__(16) uint32_t g_w1[NG * KQ * 64];    // [g][code][pos32 d pairs]
__device__ __align__(16) uint32_t g_wt[NG * SDQ * 256];  // [g][d][pos32 code pairs]

// ------------------------------ helpers ------------------------------------
__device__ __forceinline__ int inv16(int o) {
    return (((o >> 1) & 1) << 4) | ((o & 1) << 3) | (((o >> 2) & 3) << 1);
}
__device__ __forceinline__ uint32_t pk(float lo, float hi) {
    __half2 h = __floats2half2_rn(lo, hi);
    return *reinterpret_cast<uint32_t*>(&h);
}
__device__ __forceinline__ float fexp(float x) {   // FMA-only exp
    float y = x * 1.4426950408889634f;
    float n = rintf(y);
    float f = y - n;
    float p = 1.3333558146428443e-3f;
    p = fmaf(p, f, 9.618129107628477e-3f);
    p = fmaf(p, f, 5.550410866482158e-2f);
    p = fmaf(p, f, 2.402265069591007e-1f);
    p = fmaf(p, f, 6.931471805599453e-1f);
    p = fmaf(p, f, 1.0f);
    return p * __int_as_float(((int)n + 127) << 23);
}
__device__ __forceinline__ void mma_f16(float* c,
                                        uint32_t a0, uint32_t a1, uint32_t a2, uint32_t a3,
                                        uint32_t b0, uint32_t b1) {
    asm volatile(
        "mma.sync.aligned.m16n8k16.row.col.f32.f16.f16.f32 "
        "{%0,%1,%2,%3}, {%4,%5,%6,%7}, {%8,%9}, {%0,%1,%2,%3};\n"
        : "+f"(c[0]), "+f"(c[1]), "+f"(c[2]), "+f"(c[3])
        : "r"(a0), "r"(a1), "r"(a2), "r"(a3), "r"(b0), "r"(b1));
}
__device__ __forceinline__ uint32_t smem_u32(const void* p) {
    uint32_t a;
    asm("{ .reg .u64 t; cvta.to.shared.u64 t, %1; cvt.u32.u64 %0, t; }"
        : "=r"(a) : "l"(p));
    return a;
}
__device__ __forceinline__ void cpa16(uint32_t dst, const void* src) {
    asm volatile("cp.async.cg.shared.global [%0], [%1], 16;" :: "r"(dst), "l"(src));
}
#define CP_COMMIT() asm volatile("cp.async.commit_group;" ::: "memory")
#define CP_WAIT1()  asm volatile("cp.async.wait_group 1;" ::: "memory")

__device__ __forceinline__ const float* pick_w(const float* w0, const float* w1,
                                               const float* w2, const float* w3, int g) {
    return (g == 0) ? w0 : ((g == 1) ? w1 : ((g == 2) ? w2 : w3));
}

// ---------------------------------------------------------------------------
// prep: 64 blocks = (g, kt, quarter). csq + g_w1 + g_wt + zero g_avg.
// ---------------------------------------------------------------------------
__global__ void gsm4_prep_kernel(const float* __restrict__ w0, const float* __restrict__ w1,
                                 const float* __restrict__ w2, const float* __restrict__ w3) {
    extern __shared__ float sw[];                  // [128][132] raw f32 tile
    const int bx = blockIdx.x;
    const int g  = bx >> 4;
    const int kt = (bx >> 2) & 3;
    const int q  = bx & 3;
    const int tid = threadIdx.x;
    const float* W = pick_w(w0, w1, w2, w3, g) + (size_t)kt * 128 * SDQ;

    #pragma unroll
    for (int j = 0; j < 16; j++) {
        int i = tid + 256 * j;
        int k = i >> 5, dq = (i & 31) * 4;
        *(float4*)(sw + k * 132 + dq) = *(const float4*)(W + (size_t)k * SDQ + dq);
    }
    if (bx == 0) {
        #pragma unroll
        for (int j = 0; j < 8; j++) g_avg[tid + 256 * j] = 0.f;
    }
    __syncthreads();

    if (tid < 32) {
        int k = 32 * q + tid;
        const float* r = sw + k * 132;
        float s0 = 0.f, s1 = 0.f, s2 = 0.f, s3 = 0.f;
        #pragma unroll 8
        for (int d = 0; d < SDQ; d += 4) {
            s0 = fmaf(r[d], r[d], s0);
            s1 = fmaf(r[d + 1], r[d + 1], s1);
            s2 = fmaf(r[d + 2], r[d + 2], s2);
            s3 = fmaf(r[d + 3], r[d + 3], s3);
        }
        g_csq[g * KQ + kt * 128 + k] = (s0 + s1) + (s2 + s3);
    }

    #pragma unroll
    for (int j = 0; j < 8; j++) {
        int idx = tid + 256 * j;
        int k = 32 * q + (idx >> 6);
        int o = idx & 63;
        int d0 = (o >> 4) * 32 + inv16(o & 15);
        g_w1[((size_t)(g * KQ + kt * 128 + k)) * 64 + o] =
            pk(sw[k * 132 + d0], sw[k * 132 + d0 + 1]);
    }
    #pragma unroll
    for (int j = 0; j < 8; j++) {
        int idx = tid + 256 * j;
        int d = 32 * q + (idx >> 6);
        int o = idx & 63;
        int lc = (o >> 4) * 32 + inv16(o & 15);
        g_wt[((size_t)(g * SDQ + d)) * 256 + kt * 64 + o] =
            pk(sw[lc * 132 + d], sw[(lc + 1) * 132 + d]);
    }
}

// ---------------------------------------------------------------------------
// fused main kernel: CTA = (group g, 128-token tile), 512 threads / 16 warps
// warp: wm = wid>>1 (rows 16*wm..+16), wq = wid&1 (code/d half)
// ---------------------------------------------------------------------------
__global__ __launch_bounds__(NTHR, 1)
void gsm4_fused_kernel(const float* __restrict__ x,
                       const float* __restrict__ gum,
                       float* __restrict__ out) {
    extern __shared__ char smc[];
    const uint32_t smb = smem_u32(smc);
    const int g  = blockIdx.y;
    const int n0 = blockIdx.x * TM;
    const int b  = n0 / TQ;
    const int t0 = n0 % TQ;

    const int tid  = threadIdx.x;
    const int wid  = tid >> 5;
    const int lane = tid & 31;
    const int lg   = lane >> 2;
    const int lt   = lane & 3;
    const int wm   = wid >> 1;
    const int wq   = wid & 1;
    const int m0   = wm * 16;

    uint32_t* sP   = (uint32_t*)(smc + OFF_P);
    float* sX      = (float*)(smc + OFF_P);        // overlay (stride SXS)
    float* sCsq    = (float*)(smc + OFF_CSQ);
    float* sRs     = (float*)(smc + OFF_RS);
    float* sRinv   = (float*)(smc + OFF_RI);

    // chunk loader: cc<8 -> w1[cc] (64x256B), else wt[cc-8] (128x128B)
    auto cp_chunk = [&](int cc, int buf) {
        uint32_t dst = smb + OFF_WB + buf * WBUF;
        if (cc < 8) {
            const char* s1 = (const char*)g_w1 + ((size_t)(g * KQ + cc * 64)) * 256;
            #pragma unroll
            for (int j = 0; j < 2; j++) {
                int i = tid + NTHR * j;
                int r = i >> 4, o = i & 15;
                cpa16(dst + r * W1B + o * 16, s1 + (size_t)r * 256 + o * 16);
            }
        } else {
            const char* s2 = (const char*)g_wt + ((size_t)(g * SDQ)) * 1024 + (cc - 8) * 128;
            #pragma unroll
            for (int j = 0; j < 2; j++) {
                int i = tid + NTHR * j;
                int r = i >> 3, o = i & 7;
                cpa16(dst + r * W2B + o * 16, s2 + (size_t)r * 1024 + o * 16);
            }
        }
    };

    // prologue --------------------------------------------------------------
    cp_chunk(0, 0);
    CP_COMMIT();
    cp_chunk(1, 1);
    CP_COMMIT();

    sCsq[tid] = 0.5f * g_csq[g * KQ + tid];
    if (tid < TM) sRs[tid] = 0.f;

    {
        const float* xb = x + ((size_t)(b * 512 + g * SDQ)) * TQ + t0;
        #pragma unroll
        for (int j = 0; j < 8; j++) {
            int i = tid + NTHR * j;
            int d = i >> 5, mq = (i & 31) * 4;
            *(float4*)(sX + d * SXS + mq) = *(const float4*)(xb + (size_t)d * TQ + mq);
        }
    }
    __syncthreads();

    // A fragments (GEMM1): 8 k16-steps x 4 half2 regs -----------------------
    uint32_t af[8][4];
    #pragma unroll
    for (int s = 0; s < 8; s++) {
        int dbs = 16 * s + 2 * lt;
        af[s][0] = pk(sX[dbs * SXS + m0 + lg],           sX[(dbs + 1) * SXS + m0 + lg]);
        af[s][1] = pk(sX[dbs * SXS + m0 + lg + 8],       sX[(dbs + 1) * SXS + m0 + lg + 8]);
        af[s][2] = pk(sX[(dbs + 8) * SXS + m0 + lg],     sX[(dbs + 9) * SXS + m0 + lg]);
        af[s][3] = pk(sX[(dbs + 8) * SXS + m0 + lg + 8], sX[(dbs + 9) * SXS + m0 + lg + 8]);
    }
    __syncthreads();                                // sX dead -> sP region

    const float* gmr = gum + ((size_t)g * NTOK + n0 + m0 + lg) * KQ + wq * 32 + 2 * lt;

    // ---------------- unified loop: 8 GEMM1 chunks, 8 GEMM2 chunks ---------
    float rs0 = 0.f, rs1 = 0.f;
    float qa[8][4];
    #pragma unroll
    for (int t = 0; t < 8; t++)
        #pragma unroll
        for (int e = 0; e < 4; e++) qa[t][e] = 0.f;

    for (int cc = 0; cc < 16; cc++) {
        CP_WAIT1();
        __syncthreads();
        if (cc + 2 < 16) { cp_chunk(cc + 2, (cc + 2) % 3); CP_COMMIT(); }
        const char* wb = smc + OFF_WB + (cc % 3) * WBUF;

        if (cc < 8) {
            // gumbel for this chunk (covered by the 32 mma below)
            float2 gv[8];
            {
                const float* p0 = gmr + cc * 64;
                #pragma unroll
                for (int t = 0; t < 4; t++) {
                    gv[t]     = *(const float2*)(p0 + 8 * t);
                    gv[4 + t] = *(const float2*)(p0 + 8 * KQ + 8 * t);
                }
            }
            // GEMM1 chunk cc: 4 n8-tiles (codes 64cc+32wq+8t)
            float acc[4][4];
            #pragma unroll
            for (int t = 0; t < 4; t++)
                #pragma unroll
                for (int e = 0; e < 4; e++) acc[t][e] = 0.f;
            #pragma unroll
            for (int kg = 0; kg < 4; kg++) {
                #pragma unroll
                for (int t = 0; t < 4; t++) {
                    uint4 B = *(const uint4*)(wb + (wq * 32 + t * 8 + lg) * W1B + kg * 64 + lt * 16);
                    mma_f16(acc[t], af[2 * kg][0], af[2 * kg][1], af[2 * kg][2], af[2 * kg][3], B.x, B.y);
                    mma_f16(acc[t], af[2 * kg + 1][0], af[2 * kg + 1][1], af[2 * kg + 1][2], af[2 * kg + 1][3], B.z, B.w);
                }
            }
            // fused exp epilogue -> sP (STS.128 per row-group)
            uint4 ua, ub;
            uint32_t* pu_a = &ua.x;
            uint32_t* pu_b = &ub.x;
            #pragma unroll
            for (int t = 0; t < 4; t++) {
                float2 cs = *(const float2*)(sCsq + cc * 64 + wq * 32 + 8 * t + 2 * lt);
                float p0v = fexp(acc[t][0] - cs.x + 0.5f * gv[t].x);
                float p1v = fexp(acc[t][1] - cs.y + 0.5f * gv[t].y);
                float p2v = fexp(acc[t][2] - cs.x + 0.5f * gv[4 + t].x);
                float p3v = fexp(acc[t][3] - cs.y + 0.5f * gv[4 + t].y);
                rs0 += p0v + p1v;
                rs1 += p2v + p3v;
                pu_a[t] = pk(p0v, p1v);
                pu_b[t] = pk(p2v, p3v);
            }
            const int wbase = (m0 + lg) * PSW + cc * 32 + wq * 16 + 4 * lt;
            *(uint4*)(sP + wbase)           = ua;
            *(uint4*)(sP + wbase + 8 * PSW) = ub;
        } else {
            // GEMM2 chunk c = cc-8: 8 n8-tiles (d = 64wq + 8t), A from sP
            const int c = cc - 8;
            #pragma unroll
            for (int g2 = 0; g2 < 2; g2++) {
                uint4 U = *(const uint4*)(sP + (m0 + lg) * PSW + (c * 2 + g2) * 16 + 4 * lt);
                uint4 V = *(const uint4*)(sP + (m0 + lg + 8) * PSW + (c * 2 + g2) * 16 + 4 * lt);
                #pragma unroll
                for (int t = 0; t < 8; t++) {
                    uint4 B = *(const uint4*)(wb + (wq * 64 + t * 8 + lg) * W2B + g2 * 64 + lt * 16);
                    mma_f16(qa[t], U.x, V.x, U.y, V.y, B.x, B.y);
                    mma_f16(qa[t], U.z, V.z, U.w, V.w, B.z, B.w);
                }
            }
        }
    }

    // rowsums ---------------------------------------------------------------
    rs0 += __shfl_xor_sync(0xffffffffu, rs0, 1);
    rs0 += __shfl_xor_sync(0xffffffffu, rs0, 2);
    rs1 += __shfl_xor_sync(0xffffffffu, rs1, 1);
    rs1 += __shfl_xor_sync(0xffffffffu, rs1, 2);
    if (lt == 0) {
        atomicAdd(&sRs[m0 + lg], rs0);
        atomicAdd(&sRs[m0 + lg + 8], rs1);
    }
    __syncthreads();
    if (tid < TM) sRinv[tid] = 1.0f / sRs[tid];
    __syncthreads();

    // avg_probs: thread pair per packed word column -------------------------
    {
        int w = tid >> 1;
        int rb = (tid & 1) * 64;
        float s0 = 0.f, s1 = 0.f;
        #pragma unroll 8
        for (int r = 0; r < 64; r++) {
            uint32_t u = sP[(rb + r) * PSW + w];
            __half2 h = *reinterpret_cast<__half2*>(&u);
            float2 f = __half22float2(h);
            float ri = sRinv[rb + r];
            s0 = fmaf(f.x, ri, s0);
            s1 = fmaf(f.y, ri, s1);
        }
        s0 += __shfl_xor_sync(0xffffffffu, s0, 1);
        s1 += __shfl_xor_sync(0xffffffffu, s1, 1);
        if (!(tid & 1)) {
            int o = w & 15;
            int k0 = (w >> 4) * 32 + inv16(o);
            atomicAdd(&g_avg[g * KQ + k0], s0);
            atomicAdd(&g_avg[g * KQ + k0 + 1], s1);
        }
    }
    __syncthreads();                                // sP free for staging

    // epilogue: normalize, transpose via smem, coalesced STG.128 ------------
    {
        float* stage = (float*)(smc + OFF_P);       // [128 d][SXS]
        const float r1v = sRinv[m0 + lg];
        const float r2v = sRinv[m0 + lg + 8];
        #pragma unroll
        for (int t = 0; t < 8; t++) {
            int d = wq * 64 + t * 8 + 2 * lt;
            stage[d * SXS + m0 + lg]           = qa[t][0] * r1v;
            stage[(d + 1) * SXS + m0 + lg]     = qa[t][1] * r1v;
            stage[d * SXS + m0 + lg + 8]       = qa[t][2] * r2v;
            stage[(d + 1) * SXS + m0 + lg + 8] = qa[t][3] * r2v;
        }
        __syncthreads();
        #pragma unroll
        for (int j = 0; j < 8; j++) {
            int i = tid + NTHR * j;
            int d = i >> 5, mq = (i & 31) * 4;
            float4 v = *(const float4*)(stage + d * SXS + mq);
            *(float4*)(out + ((size_t)(b * 512 + g * SDQ + d)) * TQ + t0 + mq) = v;
        }
    }
}

// ---------------------------------------------------------------------------
// perplexity
// ---------------------------------------------------------------------------
__global__ void gsm4_perp_kernel(float* __restrict__ out) {
    __shared__ float se[NG];
    int w = threadIdx.x >> 5;
    int lane = threadIdx.x & 31;
    float acc = 0.f;
    for (int k = lane; k < KQ; k += 32) {
        float a = g_avg[w * KQ + k] * (1.0f / (float)NTOK);
        acc += a * logf(a + 1e-10f);
    }
    #pragma unroll
    for (int o = 16; o; o >>= 1) acc += __shfl_xor_sync(0xffffffffu, acc, o);
    if (lane == 0) se[w] = acc;
    __syncthreads();
    if (threadIdx.x == 0) {
        float p = 0.f;
        #pragma unroll
        for (int gg = 0; gg < NG; gg++) p += expf(-se[gg]);
        out[QUANT_ELEMS] = p;
    }
}

// ---------------------------------------------------------------------------
extern "C" void kernel_launch(void* const* d_in, const int* in_sizes, int n_in,
                              void* d_out, int out_size) {
    const float* x   = (const float*)d_in[0];
    const float* w0  = (const float*)d_in[1];
    const float* w1  = (const float*)d_in[2];
    const float* w2  = (const float*)d_in[3];
    const float* w3  = (const float*)d_in[4];
    const float* gum = (const float*)d_in[5];
    float* out = (float*)d_out;

    cudaFuncSetAttribute(gsm4_prep_kernel,
                         cudaFuncAttributeMaxDynamicSharedMemorySize, 128 * 132 * 4);
    cudaFuncSetAttribute(gsm4_fused_kernel,
                         cudaFuncAttributeMaxDynamicSharedMemorySize, SMEM_BYTES);

    gsm4_prep_kernel<<<64, 256, 128 * 132 * 4>>>(w0, w1, w2, w3);

    dim3 grid(NTOK / TM, NG);
    gsm4_fused_kernel<<<grid, NTHR, SMEM_BYTES>>>(x, gum, out);

    if (out_size > QUANT_ELEMS) {
        gsm4_perp_kernel<<<1, NG * 32>>>(out);
    }
}

// round 9
// speedup vs baseline: 1.3321x; 1.0701x over previous
#include <cuda_runtime.h>
#include <cuda_fp16.h>
#include <cstdint>

// ---------------------------------------------------------------------------
// GumbelSoftmaxModule4 v9: barrier-free GEMM phases.
//   B operands via LDG.128 from global (L1-cached, shared across warps) —
//   no cp.async buffers, no per-iteration __syncthreads.
//   GEMM1 writes sP rows owned by the same warp that reads them in GEMM2.
// ---------------------------------------------------------------------------

namespace {
constexpr int KQ = 512, NG = 4, SDQ = 128, BQ = 16, TQ = 2048;
constexpr int NTOK = BQ * TQ;            // 32768
constexpr int TM   = 128;                // tokens per CTA
constexpr int NTHR = 512;                // 16 warps
constexpr int PSW  = 272;                // sP row stride (uint32 words)
constexpr int SXS  = 132;                // X / stage row stride (f32)
constexpr int OFF_P   = 0;                          // sP: 128*272*4 = 139264
constexpr int OFF_STG = 139264;                     // stage: 64*132*4 = 33792
constexpr int OFF_CSQ = OFF_STG + 33792;            // 173056: 512 f32
constexpr int OFF_RS  = OFF_CSQ + 2048;             // 128 f32
constexpr int OFF_RI  = OFF_RS + 512;               // 128 f32
constexpr int SMEM_BYTES = OFF_RI + 512;            // 176128 (L1D ~52KB left)
constexpr int QUANT_ELEMS = BQ * 512 * TQ;
}

__device__ float g_csq[NG * KQ];
__device__ float g_avg[NG * KQ];
__device__ __align__(16) uint32_t g_w1[NG * KQ * 64];    // [g][code][pos32 d pairs]
__device__ __align__(16) uint32_t g_wt[NG * SDQ * 256];  // [g][d][pos32 code pairs]

// ------------------------------ helpers ------------------------------------
__device__ __forceinline__ int inv16(int o) {
    return (((o >> 1) & 1) << 4) | ((o & 1) << 3) | (((o >> 2) & 3) << 1);
}
__device__ __forceinline__ uint32_t pk(float lo, float hi) {
    __half2 h = __floats2half2_rn(lo, hi);
    return *reinterpret_cast<uint32_t*>(&h);
}
__device__ __forceinline__ float fexp(float x) {   // FMA-only exp
    float y = x * 1.4426950408889634f;
    float n = rintf(y);
    float f = y - n;
    float p = 1.3333558146428443e-3f;
    p = fmaf(p, f, 9.618129107628477e-3f);
    p = fmaf(p, f, 5.550410866482158e-2f);
    p = fmaf(p, f, 2.402265069591007e-1f);
    p = fmaf(p, f, 6.931471805599453e-1f);
    p = fmaf(p, f, 1.0f);
    return p * __int_as_float(((int)n + 127) << 23);
}
__device__ __forceinline__ void mma_f16(float* c,
                                        uint32_t a0, uint32_t a1, uint32_t a2, uint32_t a3,
                                        uint32_t b0, uint32_t b1) {
    asm volatile(
        "mma.sync.aligned.m16n8k16.row.col.f32.f16.f16.f32 "
        "{%0,%1,%2,%3}, {%4,%5,%6,%7}, {%8,%9}, {%0,%1,%2,%3};\n"
        : "+f"(c[0]), "+f"(c[1]), "+f"(c[2]), "+f"(c[3])
        : "r"(a0), "r"(a1), "r"(a2), "r"(a3), "r"(b0), "r"(b1));
}
__device__ __forceinline__ const float* pick_w(const float* w0, const float* w1,
                                               const float* w2, const float* w3, int g) {
    return (g == 0) ? w0 : ((g == 1) ? w1 : ((g == 2) ? w2 : w3));
}

// ---------------------------------------------------------------------------
// prep: 64 blocks = (g, kt, quarter). csq + g_w1 + g_wt + zero g_avg.
// ---------------------------------------------------------------------------
__global__ void gsm4_prep_kernel(const float* __restrict__ w0, const float* __restrict__ w1,
                                 const float* __restrict__ w2, const float* __restrict__ w3) {
    extern __shared__ float sw[];                  // [128][132] raw f32 tile
    const int bx = blockIdx.x;
    const int g  = bx >> 4;
    const int kt = (bx >> 2) & 3;
    const int q  = bx & 3;
    const int tid = threadIdx.x;
    const float* W = pick_w(w0, w1, w2, w3, g) + (size_t)kt * 128 * SDQ;

    #pragma unroll
    for (int j = 0; j < 16; j++) {
        int i = tid + 256 * j;
        int k = i >> 5, dq = (i & 31) * 4;
        *(float4*)(sw + k * 132 + dq) = *(const float4*)(W + (size_t)k * SDQ + dq);
    }
    if (bx == 0) {
        #pragma unroll
        for (int j = 0; j < 8; j++) g_avg[tid + 256 * j] = 0.f;
    }
    __syncthreads();

    if (tid < 32) {
        int k = 32 * q + tid;
        const float* r = sw + k * 132;
        float s0 = 0.f, s1 = 0.f, s2 = 0.f, s3 = 0.f;
        #pragma unroll 8
        for (int d = 0; d < SDQ; d += 4) {
            s0 = fmaf(r[d], r[d], s0);
            s1 = fmaf(r[d + 1], r[d + 1], s1);
            s2 = fmaf(r[d + 2], r[d + 2], s2);
            s3 = fmaf(r[d + 3], r[d + 3], s3);
        }
        g_csq[g * KQ + kt * 128 + k] = (s0 + s1) + (s2 + s3);
    }

    #pragma unroll
    for (int j = 0; j < 8; j++) {
        int idx = tid + 256 * j;
        int k = 32 * q + (idx >> 6);
        int o = idx & 63;
        int d0 = (o >> 4) * 32 + inv16(o & 15);
        g_w1[((size_t)(g * KQ + kt * 128 + k)) * 64 + o] =
            pk(sw[k * 132 + d0], sw[k * 132 + d0 + 1]);
    }
    #pragma unroll
    for (int j = 0; j < 8; j++) {
        int idx = tid + 256 * j;
        int d = 32 * q + (idx >> 6);
        int o = idx & 63;
        int lc = (o >> 4) * 32 + inv16(o & 15);
        g_wt[((size_t)(g * SDQ + d)) * 256 + kt * 64 + o] =
            pk(sw[lc * 132 + d], sw[(lc + 1) * 132 + d]);
    }
}

// ---------------------------------------------------------------------------
// fused main kernel: CTA = (group g, 128-token tile), 512 threads / 16 warps
// warp (wm, wq): rows 16*wm..+16; wq = code-half (GEMM1) / d-half (GEMM2)
// ---------------------------------------------------------------------------
__global__ __launch_bounds__(NTHR, 1)
void gsm4_fused_kernel(const float* __restrict__ x,
                       const float* __restrict__ gum,
                       float* __restrict__ out) {
    extern __shared__ char smc[];
    const int g  = blockIdx.y;
    const int n0 = blockIdx.x * TM;
    const int b  = n0 / TQ;
    const int t0 = n0 % TQ;

    const int tid  = threadIdx.x;
    const int wid  = tid >> 5;
    const int lane = tid & 31;
    const int lg   = lane >> 2;
    const int lt   = lane & 3;
    const int wm   = wid >> 1;
    const int wq   = wid & 1;
    const int m0   = wm * 16;

    uint32_t* sP   = (uint32_t*)(smc + OFF_P);
    float* sX      = (float*)(smc + OFF_P);        // overlay (stride SXS)
    float* sStage  = (float*)(smc + OFF_STG);      // [64 d][SXS]
    float* sCsq    = (float*)(smc + OFF_CSQ);
    float* sRs     = (float*)(smc + OFF_RS);
    float* sRinv   = (float*)(smc + OFF_RI);

    // prologue --------------------------------------------------------------
    sCsq[tid] = 0.5f * g_csq[g * KQ + tid];
    if (tid < TM) sRs[tid] = 0.f;

    {
        const float* xb = x + ((size_t)(b * 512 + g * SDQ)) * TQ + t0;
        #pragma unroll
        for (int j = 0; j < 8; j++) {
            int i = tid + NTHR * j;
            int d = i >> 5, mq = (i & 31) * 4;
            *(float4*)(sX + d * SXS + mq) = *(const float4*)(xb + (size_t)d * TQ + mq);
        }
    }
    __syncthreads();

    // A fragments (GEMM1): 8 k16-steps x 4 half2 regs -----------------------
    uint32_t af[8][4];
    #pragma unroll
    for (int s = 0; s < 8; s++) {
        int dbs = 16 * s + 2 * lt;
        af[s][0] = pk(sX[dbs * SXS + m0 + lg],           sX[(dbs + 1) * SXS + m0 + lg]);
        af[s][1] = pk(sX[dbs * SXS + m0 + lg + 8],       sX[(dbs + 1) * SXS + m0 + lg + 8]);
        af[s][2] = pk(sX[(dbs + 8) * SXS + m0 + lg],     sX[(dbs + 9) * SXS + m0 + lg]);
        af[s][3] = pk(sX[(dbs + 8) * SXS + m0 + lg + 8], sX[(dbs + 9) * SXS + m0 + lg + 8]);
    }
    __syncthreads();                                // sX dead -> sP region

    const float* gmr = gum + ((size_t)g * NTOK + n0 + m0 + lg) * KQ + wq * 32 + 2 * lt;
    // per-warp B base pointers (global, L1-cached)
    const uint32_t* w1b = g_w1 + ((size_t)(g * KQ + wq * 32 + lg)) * 64 + lt * 4;
    const uint32_t* wtb = g_wt + ((size_t)(g * SDQ + wq * 64 + lg)) * 256 + lt * 4;

    // ---------------- GEMM1 + fused exp: barrier-free ----------------------
    float rs0 = 0.f, rs1 = 0.f;
    for (int c = 0; c < 8; c++) {
        float acc[4][4];
        #pragma unroll
        for (int t = 0; t < 4; t++)
            #pragma unroll
            for (int e = 0; e < 4; e++) acc[t][e] = 0.f;

        #pragma unroll
        for (int kg = 0; kg < 4; kg++) {
            #pragma unroll
            for (int t = 0; t < 4; t++) {
                uint4 B = *(const uint4*)(w1b + ((size_t)(c * 64 + t * 8)) * 64 + kg * 16);
                mma_f16(acc[t], af[2 * kg][0], af[2 * kg][1], af[2 * kg][2], af[2 * kg][3], B.x, B.y);
                mma_f16(acc[t], af[2 * kg + 1][0], af[2 * kg + 1][1], af[2 * kg + 1][2], af[2 * kg + 1][3], B.z, B.w);
            }
        }
        // gumbel + fused exp -> sP (own rows; fire-and-forget)
        float2 gv[8];
        {
            const float* p0 = gmr + c * 64;
            #pragma unroll
            for (int t = 0; t < 4; t++) {
                gv[t]     = *(const float2*)(p0 + 8 * t);
                gv[4 + t] = *(const float2*)(p0 + 8 * KQ + 8 * t);
            }
        }
        uint4 ua, ub;
        uint32_t* pu_a = &ua.x;
        uint32_t* pu_b = &ub.x;
        #pragma unroll
        for (int t = 0; t < 4; t++) {
            float2 cs = *(const float2*)(sCsq + c * 64 + wq * 32 + 8 * t + 2 * lt);
            float p0v = fexp(acc[t][0] - cs.x + 0.5f * gv[t].x);
            float p1v = fexp(acc[t][1] - cs.y + 0.5f * gv[t].y);
            float p2v = fexp(acc[t][2] - cs.x + 0.5f * gv[4 + t].x);
            float p3v = fexp(acc[t][3] - cs.y + 0.5f * gv[4 + t].y);
            rs0 += p0v + p1v;
            rs1 += p2v + p3v;
            pu_a[t] = pk(p0v, p1v);
            pu_b[t] = pk(p2v, p3v);
        }
        const int wbase = (m0 + lg) * PSW + c * 32 + wq * 16 + 4 * lt;
        *(uint4*)(sP + wbase)           = ua;
        *(uint4*)(sP + wbase + 8 * PSW) = ub;
    }
    // rowsum partials (no barrier needed before GEMM2) ----------------------
    rs0 += __shfl_xor_sync(0xffffffffu, rs0, 1);
    rs0 += __shfl_xor_sync(0xffffffffu, rs0, 2);
    rs1 += __shfl_xor_sync(0xffffffffu, rs1, 1);
    rs1 += __shfl_xor_sync(0xffffffffu, rs1, 2);
    if (lt == 0) {
        atomicAdd(&sRs[m0 + lg], rs0);
        atomicAdd(&sRs[m0 + lg + 8], rs1);
    }

    // ---------------- GEMM2: barrier-free, A = own sP rows -----------------
    float qa[8][4];
    #pragma unroll
    for (int t = 0; t < 8; t++)
        #pragma unroll
        for (int e = 0; e < 4; e++) qa[t][e] = 0.f;

    for (int c = 0; c < 8; c++) {
        #pragma unroll
        for (int g2 = 0; g2 < 2; g2++) {
            uint4 U = *(const uint4*)(sP + (m0 + lg) * PSW + (c * 2 + g2) * 16 + 4 * lt);
            uint4 V = *(const uint4*)(sP + (m0 + lg + 8) * PSW + (c * 2 + g2) * 16 + 4 * lt);
            #pragma unroll
            for (int t = 0; t < 8; t++) {
                uint4 B = *(const uint4*)(wtb + ((size_t)(t * 8)) * 256 + c * 32 + g2 * 16);
                mma_f16(qa[t], U.x, V.x, U.y, V.y, B.x, B.y);
                mma_f16(qa[t], U.z, V.z, U.w, V.w, B.z, B.w);
            }
        }
    }
    __syncthreads();                                // rowsum atomics visible
    if (tid < TM) sRinv[tid] = 1.0f / sRs[tid];
    __syncthreads();

    // avg_probs: thread pair per packed word column -------------------------
    {
        int w = tid >> 1;
        int rb = (tid & 1) * 64;
        float s0 = 0.f, s1 = 0.f;
        #pragma unroll 8
        for (int r = 0; r < 64; r++) {
            uint32_t u = sP[(rb + r) * PSW + w];
            __half2 h = *reinterpret_cast<__half2*>(&u);
            float2 f = __half22float2(h);
            float ri = sRinv[rb + r];
            s0 = fmaf(f.x, ri, s0);
            s1 = fmaf(f.y, ri, s1);
        }
        s0 += __shfl_xor_sync(0xffffffffu, s0, 1);
        s1 += __shfl_xor_sync(0xffffffffu, s1, 1);
        if (!(tid & 1)) {
            int o = w & 15;
            int k0 = (w >> 4) * 32 + inv16(o);
            atomicAdd(&g_avg[g * KQ + k0], s0);
            atomicAdd(&g_avg[g * KQ + k0 + 1], s1);
        }
    }

    // epilogue: two 64-d staging passes, coalesced STG.128 ------------------
    const float r1v = sRinv[m0 + lg];
    const float r2v = sRinv[m0 + lg + 8];
    #pragma unroll
    for (int h = 0; h < 2; h++) {
        __syncthreads();                            // stage free / prev pass done
        if (wq == h) {
            #pragma unroll
            for (int t = 0; t < 8; t++) {
                int d = t * 8 + 2 * lt;             // local d within half
                sStage[d * SXS + m0 + lg]           = qa[t][0] * r1v;
                sStage[(d + 1) * SXS + m0 + lg]     = qa[t][1] * r1v;
                sStage[d * SXS + m0 + lg + 8]       = qa[t][2] * r2v;
                sStage[(d + 1) * SXS + m0 + lg + 8] = qa[t][3] * r2v;
            }
        }
        __syncthreads();
        float* ob = out + ((size_t)(b * 512 + g * SDQ + h * 64)) * TQ + t0;
        #pragma unroll
        for (int j = 0; j < 4; j++) {
            int i = tid + NTHR * j;
            int d = i >> 5, mq = (i & 31) * 4;
            float4 v = *(const float4*)(sStage + d * SXS + mq);
            *(float4*)(ob + (size_t)d * TQ + mq) = v;
        }
    }
}

// ---------------------------------------------------------------------------
// perplexity
// ---------------------------------------------------------------------------
__global__ void gsm4_perp_kernel(float* __restrict__ out) {
    __shared__ float se[NG];
    int w = threadIdx.x >> 5;
    int lane = threadIdx.x & 31;
    float acc = 0.f;
    for (int k = lane; k < KQ; k += 32) {
        float a = g_avg[w * KQ + k] * (1.0f / (float)NTOK);
        acc += a * logf(a + 1e-10f);
    }
    #pragma unroll
    for (int o = 16; o; o >>= 1) acc += __shfl_xor_sync(0xffffffffu, acc, o);
    if (lane == 0) se[w] = acc;
    __syncthreads();
    if (threadIdx.x == 0) {
        float p = 0.f;
        #pragma unroll
        for (int gg = 0; gg < NG; gg++) p += expf(-se[gg]);
        out[QUANT_ELEMS] = p;
    }
}

// ---------------------------------------------------------------------------
extern "C" void kernel_launch(void* const* d_in, const int* in_sizes, int n_in,
                              void* d_out, int out_size) {
    const float* x   = (const float*)d_in[0];
    const float* w0  = (const float*)d_in[1];
    const float* w1  = (const float*)d_in[2];
    const float* w2  = (const float*)d_in[3];
    const float* w3  = (const float*)d_in[4];
    const float* gum = (const float*)d_in[5];
    float* out = (float*)d_out;

    cudaFuncSetAttribute(gsm4_prep_kernel,
                         cudaFuncAttributeMaxDynamicSharedMemorySize, 128 * 132 * 4);
    cudaFuncSetAttribute(gsm4_fused_kernel,
                         cudaFuncAttributeMaxDynamicSharedMemorySize, SMEM_BYTES);

    gsm4_prep_kernel<<<64, 256, 128 * 132 * 4>>>(w0, w1, w2, w3);

    dim3 grid(NTOK / TM, NG);
    gsm4_fused_kernel<<<grid, NTHR, SMEM_BYTES>>>(x, gum, out);

    if (out_size > QUANT_ELEMS) {
        gsm4_perp_kernel<<<1, NG * 32>>>(out);
    }
}

// round 10
// speedup vs baseline: 1.3916x; 1.0447x over previous
#include <cuda_runtime.h>
#include <cuda_fp16.h>
#include <cstdint>

// ---------------------------------------------------------------------------
// GumbelSoftmaxModule4 v10: v9 barrier-free scheme at occupancy 2.
//   TM=64 tokens/CTA, 256 threads, smem 72.5KB -> 2 CTAs/SM; per-CTA serial
//   phases (prologue/avg/epilogue) overlap the co-resident CTA's GEMMs.
// ---------------------------------------------------------------------------

namespace {
constexpr int KQ = 512, NG = 4, SDQ = 128, BQ = 16, TQ = 2048;
constexpr int NTOK = BQ * TQ;            // 32768
constexpr int TM   = 64;                 // tokens per CTA
constexpr int NTHR = 256;                // 8 warps
constexpr int PSW  = 272;                // sP row stride (uint32 words)
constexpr int SXS  = 68;                 // X / stage row stride (f32)
constexpr int OFF_P   = 0;                          // sP: 64*272*4 = 69632
constexpr int OFF_CSQ = 69632;                      // 512 f32
constexpr int OFF_RS  = OFF_CSQ + 2048;             // 64 f32
constexpr int OFF_RI  = OFF_RS + 256;               // 64 f32
constexpr int SMEM_BYTES = OFF_RI + 256;            // 72192 -> occ 2
constexpr int QUANT_ELEMS = BQ * 512 * TQ;
}

__device__ float g_csq[NG * KQ];
__device__ float g_avg[NG * KQ];
__device__ __align__(16) uint32_t g_w1[NG * KQ * 64];    // [g][code][pos32 d pairs]
__device__ __align__(16) uint32_t g_wt[NG * SDQ * 256];  // [g][d][pos32 code pairs]

// ------------------------------ helpers ------------------------------------
__device__ __forceinline__ int inv16(int o) {
    return (((o >> 1) & 1) << 4) | ((o & 1) << 3) | (((o >> 2) & 3) << 1);
}
__device__ __forceinline__ uint32_t pk(float lo, float hi) {
    __half2 h = __floats2half2_rn(lo, hi);
    return *reinterpret_cast<uint32_t*>(&h);
}
__device__ __forceinline__ float fexp(float x) {   // FMA-only exp
    float y = x * 1.4426950408889634f;
    float n = rintf(y);
    float f = y - n;
    float p = 1.3333558146428443e-3f;
    p = fmaf(p, f, 9.618129107628477e-3f);
    p = fmaf(p, f, 5.550410866482158e-2f);
    p = fmaf(p, f, 2.402265069591007e-1f);
    p = fmaf(p, f, 6.931471805599453e-1f);
    p = fmaf(p, f, 1.0f);
    return p * __int_as_float(((int)n + 127) << 23);
}
__device__ __forceinline__ void mma_f16(float* c,
                                        uint32_t a0, uint32_t a1, uint32_t a2, uint32_t a3,
                                        uint32_t b0, uint32_t b1) {
    asm volatile(
        "mma.sync.aligned.m16n8k16.row.col.f32.f16.f16.f32 "
        "{%0,%1,%2,%3}, {%4,%5,%6,%7}, {%8,%9}, {%0,%1,%2,%3};\n"
        : "+f"(c[0]), "+f"(c[1]), "+f"(c[2]), "+f"(c[3])
        : "r"(a0), "r"(a1), "r"(a2), "r"(a3), "r"(b0), "r"(b1));
}
__device__ __forceinline__ const float* pick_w(const float* w0, const float* w1,
                                               const float* w2, const float* w3, int g) {
    return (g == 0) ? w0 : ((g == 1) ? w1 : ((g == 2) ? w2 : w3));
}

// ---------------------------------------------------------------------------
// prep: 64 blocks = (g, kt, quarter). csq + g_w1 + g_wt + zero g_avg.
// ---------------------------------------------------------------------------
__global__ void gsm4_prep_kernel(const float* __restrict__ w0, const float* __restrict__ w1,
                                 const float* __restrict__ w2, const float* __restrict__ w3) {
    extern __shared__ float sw[];                  // [128][132] raw f32 tile
    const int bx = blockIdx.x;
    const int g  = bx >> 4;
    const int kt = (bx >> 2) & 3;
    const int q  = bx & 3;
    const int tid = threadIdx.x;
    const float* W = pick_w(w0, w1, w2, w3, g) + (size_t)kt * 128 * SDQ;

    #pragma unroll
    for (int j = 0; j < 16; j++) {
        int i = tid + 256 * j;
        int k = i >> 5, dq = (i & 31) * 4;
        *(float4*)(sw + k * 132 + dq) = *(const float4*)(W + (size_t)k * SDQ + dq);
    }
    if (bx == 0) {
        #pragma unroll
        for (int j = 0; j < 8; j++) g_avg[tid + 256 * j] = 0.f;
    }
    __syncthreads();

    if (tid < 32) {
        int k = 32 * q + tid;
        const float* r = sw + k * 132;
        float s0 = 0.f, s1 = 0.f, s2 = 0.f, s3 = 0.f;
        #pragma unroll 8
        for (int d = 0; d < SDQ; d += 4) {
            s0 = fmaf(r[d], r[d], s0);
            s1 = fmaf(r[d + 1], r[d + 1], s1);
            s2 = fmaf(r[d + 2], r[d + 2], s2);
            s3 = fmaf(r[d + 3], r[d + 3], s3);
        }
        g_csq[g * KQ + kt * 128 + k] = (s0 + s1) + (s2 + s3);
    }

    #pragma unroll
    for (int j = 0; j < 8; j++) {
        int idx = tid + 256 * j;
        int k = 32 * q + (idx >> 6);
        int o = idx & 63;
        int d0 = (o >> 4) * 32 + inv16(o & 15);
        g_w1[((size_t)(g * KQ + kt * 128 + k)) * 64 + o] =
            pk(sw[k * 132 + d0], sw[k * 132 + d0 + 1]);
    }
    #pragma unroll
    for (int j = 0; j < 8; j++) {
        int idx = tid + 256 * j;
        int d = 32 * q + (idx >> 6);
        int o = idx & 63;
        int lc = (o >> 4) * 32 + inv16(o & 15);
        g_wt[((size_t)(g * SDQ + d)) * 256 + kt * 64 + o] =
            pk(sw[lc * 132 + d], sw[(lc + 1) * 132 + d]);
    }
}

// ---------------------------------------------------------------------------
// fused main kernel: CTA = (group g, 64-token tile), 256 threads / 8 warps
// warp (wm, wq): rows 16*wm..+16; wq = code-half (GEMM1) / d-half (GEMM2)
// ---------------------------------------------------------------------------
__global__ __launch_bounds__(NTHR, 2)
void gsm4_fused_kernel(const float* __restrict__ x,
                       const float* __restrict__ gum,
                       float* __restrict__ out) {
    extern __shared__ char smc[];
    const int g  = blockIdx.y;
    const int n0 = blockIdx.x * TM;
    const int b  = n0 / TQ;
    const int t0 = n0 % TQ;

    const int tid  = threadIdx.x;
    const int wid  = tid >> 5;
    const int lane = tid & 31;
    const int lg   = lane >> 2;
    const int lt   = lane & 3;
    const int wm   = wid >> 1;
    const int wq   = wid & 1;
    const int m0   = wm * 16;

    uint32_t* sP   = (uint32_t*)(smc + OFF_P);
    float* sX      = (float*)(smc + OFF_P);        // overlay (stride SXS)
    float* sCsq    = (float*)(smc + OFF_CSQ);
    float* sRs     = (float*)(smc + OFF_RS);
    float* sRinv   = (float*)(smc + OFF_RI);

    // prologue --------------------------------------------------------------
    sCsq[tid] = 0.5f * g_csq[g * KQ + tid];
    sCsq[tid + 256] = 0.5f * g_csq[g * KQ + tid + 256];
    if (tid < TM) sRs[tid] = 0.f;

    {
        const float* xb = x + ((size_t)(b * 512 + g * SDQ)) * TQ + t0;
        #pragma unroll
        for (int j = 0; j < 8; j++) {
            int i = tid + NTHR * j;
            int d = i >> 4, mq = (i & 15) * 4;
            *(float4*)(sX + d * SXS + mq) = *(const float4*)(xb + (size_t)d * TQ + mq);
        }
    }
    __syncthreads();

    // A fragments (GEMM1): 8 k16-steps x 4 half2 regs -----------------------
    uint32_t af[8][4];
    #pragma unroll
    for (int s = 0; s < 8; s++) {
        int dbs = 16 * s + 2 * lt;
        af[s][0] = pk(sX[dbs * SXS + m0 + lg],           sX[(dbs + 1) * SXS + m0 + lg]);
        af[s][1] = pk(sX[dbs * SXS + m0 + lg + 8],       sX[(dbs + 1) * SXS + m0 + lg + 8]);
        af[s][2] = pk(sX[(dbs + 8) * SXS + m0 + lg],     sX[(dbs + 9) * SXS + m0 + lg]);
        af[s][3] = pk(sX[(dbs + 8) * SXS + m0 + lg + 8], sX[(dbs + 9) * SXS + m0 + lg + 8]);
    }
    __syncthreads();                                // sX dead -> sP region

    const float* gmr = gum + ((size_t)g * NTOK + n0 + m0 + lg) * KQ + wq * 32 + 2 * lt;
    const uint32_t* w1b = g_w1 + ((size_t)(g * KQ + wq * 32 + lg)) * 64 + lt * 4;
    const uint32_t* wtb = g_wt + ((size_t)(g * SDQ + wq * 64 + lg)) * 256 + lt * 4;

    // ---------------- GEMM1 + fused exp: barrier-free ----------------------
    float rs0 = 0.f, rs1 = 0.f;
    for (int c = 0; c < 8; c++) {
        float acc[4][4];
        #pragma unroll
        for (int t = 0; t < 4; t++)
            #pragma unroll
            for (int e = 0; e < 4; e++) acc[t][e] = 0.f;

        #pragma unroll
        for (int kg = 0; kg < 4; kg++) {
            #pragma unroll
            for (int t = 0; t < 4; t++) {
                uint4 B = *(const uint4*)(w1b + ((size_t)(c * 64 + t * 8)) * 64 + kg * 16);
                mma_f16(acc[t], af[2 * kg][0], af[2 * kg][1], af[2 * kg][2], af[2 * kg][3], B.x, B.y);
                mma_f16(acc[t], af[2 * kg + 1][0], af[2 * kg + 1][1], af[2 * kg + 1][2], af[2 * kg + 1][3], B.z, B.w);
            }
        }
        float2 gv[8];
        {
            const float* p0 = gmr + c * 64;
            #pragma unroll
            for (int t = 0; t < 4; t++) {
                gv[t]     = *(const float2*)(p0 + 8 * t);
                gv[4 + t] = *(const float2*)(p0 + 8 * KQ + 8 * t);
            }
        }
        uint4 ua, ub;
        uint32_t* pu_a = &ua.x;
        uint32_t* pu_b = &ub.x;
        #pragma unroll
        for (int t = 0; t < 4; t++) {
            float2 cs = *(const float2*)(sCsq + c * 64 + wq * 32 + 8 * t + 2 * lt);
            float p0v = fexp(acc[t][0] - cs.x + 0.5f * gv[t].x);
            float p1v = fexp(acc[t][1] - cs.y + 0.5f * gv[t].y);
            float p2v = fexp(acc[t][2] - cs.x + 0.5f * gv[4 + t].x);
            float p3v = fexp(acc[t][3] - cs.y + 0.5f * gv[4 + t].y);
            rs0 += p0v + p1v;
            rs1 += p2v + p3v;
            pu_a[t] = pk(p0v, p1v);
            pu_b[t] = pk(p2v, p3v);
        }
        const int wbase = (m0 + lg) * PSW + c * 32 + wq * 16 + 4 * lt;
        *(uint4*)(sP + wbase)           = ua;
        *(uint4*)(sP + wbase + 8 * PSW) = ub;
    }
    // rowsum partials (no barrier needed before GEMM2) ----------------------
    rs0 += __shfl_xor_sync(0xffffffffu, rs0, 1);
    rs0 += __shfl_xor_sync(0xffffffffu, rs0, 2);
    rs1 += __shfl_xor_sync(0xffffffffu, rs1, 1);
    rs1 += __shfl_xor_sync(0xffffffffu, rs1, 2);
    if (lt == 0) {
        atomicAdd(&sRs[m0 + lg], rs0);
        atomicAdd(&sRs[m0 + lg + 8], rs1);
    }

    // ---------------- GEMM2: barrier-free, A = own sP rows -----------------
    float qa[8][4];
    #pragma unroll
    for (int t = 0; t < 8; t++)
        #pragma unroll
        for (int e = 0; e < 4; e++) qa[t][e] = 0.f;

    for (int c = 0; c < 8; c++) {
        #pragma unroll
        for (int g2 = 0; g2 < 2; g2++) {
            uint4 U = *(const uint4*)(sP + (m0 + lg) * PSW + (c * 2 + g2) * 16 + 4 * lt);
            uint4 V = *(const uint4*)(sP + (m0 + lg + 8) * PSW + (c * 2 + g2) * 16 + 4 * lt);
            #pragma unroll
            for (int t = 0; t < 8; t++) {
                uint4 B = *(const uint4*)(wtb + ((size_t)(t * 8)) * 256 + c * 32 + g2 * 16);
                mma_f16(qa[t], U.x, V.x, U.y, V.y, B.x, B.y);
                mma_f16(qa[t], U.z, V.z, U.w, V.w, B.z, B.w);
            }
        }
    }
    __syncthreads();                                // rowsum atomics visible
    if (tid < TM) sRinv[tid] = 1.0f / sRs[tid];
    __syncthreads();

    // avg_probs: thread per packed word column ------------------------------
    {
        int w = tid;                                // 0..255
        float s0 = 0.f, s1 = 0.f;
        #pragma unroll 8
        for (int r = 0; r < TM; r++) {
            uint32_t u = sP[r * PSW + w];
            __half2 h = *reinterpret_cast<__half2*>(&u);
            float2 f = __half22float2(h);
            float ri = sRinv[r];
            s0 = fmaf(f.x, ri, s0);
            s1 = fmaf(f.y, ri, s1);
        }
        int o = w & 15;
        int k0 = (w >> 4) * 32 + inv16(o);
        atomicAdd(&g_avg[g * KQ + k0], s0);
        atomicAdd(&g_avg[g * KQ + k0 + 1], s1);
    }
    __syncthreads();                                // sP free for staging

    // epilogue: normalize, single staging pass, coalesced STG.128 -----------
    {
        float* stage = (float*)(smc + OFF_P);       // [128 d][SXS]
        const float r1v = sRinv[m0 + lg];
        const float r2v = sRinv[m0 + lg + 8];
        #pragma unroll
        for (int t = 0; t < 8; t++) {
            int d = wq * 64 + t * 8 + 2 * lt;
            stage[d * SXS + m0 + lg]           = qa[t][0] * r1v;
            stage[(d + 1) * SXS + m0 + lg]     = qa[t][1] * r1v;
            stage[d * SXS + m0 + lg + 8]       = qa[t][2] * r2v;
            stage[(d + 1) * SXS + m0 + lg + 8] = qa[t][3] * r2v;
        }
        __syncthreads();
        float* ob = out + ((size_t)(b * 512 + g * SDQ)) * TQ + t0;
        #pragma unroll
        for (int j = 0; j < 8; j++) {
            int i = tid + NTHR * j;
            int d = i >> 4, mq = (i & 15) * 4;
            float4 v = *(const float4*)(stage + d * SXS + mq);
            *(float4*)(ob + (size_t)d * TQ + mq) = v;
        }
    }
}

// ---------------------------------------------------------------------------
// perplexity
// ---------------------------------------------------------------------------
__global__ void gsm4_perp_kernel(float* __restrict__ out) {
    __shared__ float se[NG];
    int w = threadIdx.x >> 5;
    int lane = threadIdx.x & 31;
    float acc = 0.f;
    for (int k = lane; k < KQ; k += 32) {
        float a = g_avg[w * KQ + k] * (1.0f / (float)NTOK);
        acc += a * logf(a + 1e-10f);
    }
    #pragma unroll
    for (int o = 16; o; o >>= 1) acc += __shfl_xor_sync(0xffffffffu, acc, o);
    if (lane == 0) se[w] = acc;
    __syncthreads();
    if (threadIdx.x == 0) {
        float p = 0.f;
        #pragma unroll
        for (int gg = 0; gg < NG; gg++) p += expf(-se[gg]);
        out[QUANT_ELEMS] = p;
    }
}

// ---------------------------------------------------------------------------
extern "C" void kernel_launch(void* const* d_in, const int* in_sizes, int n_in,
                              void* d_out, int out_size) {
    const float* x   = (const float*)d_in[0];
    const float* w0  = (const float*)d_in[1];
    const float* w1  = (const float*)d_in[2];
    const float* w2  = (const float*)d_in[3];
    const float* w3  = (const float*)d_in[4];
    const float* gum = (const float*)d_in[5];
    float* out = (float*)d_out;

    cudaFuncSetAttribute(gsm4_prep_kernel,
                         cudaFuncAttributeMaxDynamicSharedMemorySize, 128 * 132 * 4);
    cudaFuncSetAttribute(gsm4_fused_kernel,
                         cudaFuncAttributeMaxDynamicSharedMemorySize, SMEM_BYTES);

    gsm4_prep_kernel<<<64, 256, 128 * 132 * 4>>>(w0, w1, w2, w3);

    dim3 grid(NTOK / TM, NG);
    gsm4_fused_kernel<<<grid, NTHR, SMEM_BYTES>>>(x, gum, out);

    if (out_size > QUANT_ELEMS) {
        gsm4_perp_kernel<<<1, NG * 32>>>(out);
    }
}

// round 11
// speedup vs baseline: 1.3932x; 1.0011x over previous
#include <cuda_runtime.h>
#include <cuda_fp16.h>
#include <cstdint>

// ---------------------------------------------------------------------------
// GumbelSoftmaxModule4 v11: v10 + MUFU-based exp (ex2.approx) + perp merged
// into the fused kernel (last-CTA reduction; 2 launches total).
// ---------------------------------------------------------------------------

namespace {
constexpr int KQ = 512, NG = 4, SDQ = 128, BQ = 16, TQ = 2048;
constexpr int NTOK = BQ * TQ;            // 32768
constexpr int TM   = 64;                 // tokens per CTA
constexpr int NTHR = 256;                // 8 warps
constexpr int PSW  = 272;                // sP row stride (uint32 words)
constexpr int SXS  = 68;                 // X / stage row stride (f32)
constexpr int OFF_P   = 0;                          // sP: 64*272*4 = 69632
constexpr int OFF_CSQ = 69632;                      // 512 f32 (pre-scaled)
constexpr int OFF_RS  = OFF_CSQ + 2048;             // 64 f32
constexpr int OFF_RI  = OFF_RS + 256;               // 64 f32
constexpr int SMEM_BYTES = OFF_RI + 256;            // 72192 -> occ 2
constexpr int QUANT_ELEMS = BQ * 512 * TQ;
constexpr float L2E  = 1.4426950408889634f;
constexpr float HL2E = 0.7213475204444817f;
}

__device__ float g_csq[NG * KQ];
__device__ float g_avg[NG * KQ];
__device__ unsigned int g_ctr;
__device__ __align__(16) uint32_t g_w1[NG * KQ * 64];    // [g][code][pos32 d pairs]
__device__ __align__(16) uint32_t g_wt[NG * SDQ * 256];  // [g][d][pos32 code pairs]

// ------------------------------ helpers ------------------------------------
__device__ __forceinline__ int inv16(int o) {
    return (((o >> 1) & 1) << 4) | ((o & 1) << 3) | (((o >> 2) & 3) << 1);
}
__device__ __forceinline__ uint32_t pk(float lo, float hi) {
    __half2 h = __floats2half2_rn(lo, hi);
    return *reinterpret_cast<uint32_t*>(&h);
}
__device__ __forceinline__ float ex2(float y) {    // 2^y via MUFU
    float r;
    asm("ex2.approx.f32 %0, %1;" : "=f"(r) : "f"(y));
    return r;
}
__device__ __forceinline__ void mma_f16(float* c,
                                        uint32_t a0, uint32_t a1, uint32_t a2, uint32_t a3,
                                        uint32_t b0, uint32_t b1) {
    asm volatile(
        "mma.sync.aligned.m16n8k16.row.col.f32.f16.f16.f32 "
        "{%0,%1,%2,%3}, {%4,%5,%6,%7}, {%8,%9}, {%0,%1,%2,%3};\n"
        : "+f"(c[0]), "+f"(c[1]), "+f"(c[2]), "+f"(c[3])
        : "r"(a0), "r"(a1), "r"(a2), "r"(a3), "r"(b0), "r"(b1));
}
__device__ __forceinline__ const float* pick_w(const float* w0, const float* w1,
                                               const float* w2, const float* w3, int g) {
    return (g == 0) ? w0 : ((g == 1) ? w1 : ((g == 2) ? w2 : w3));
}

// ---------------------------------------------------------------------------
// prep: 64 blocks = (g, kt, quarter). csq + g_w1 + g_wt + zero g_avg/ctr.
// ---------------------------------------------------------------------------
__global__ void gsm4_prep_kernel(const float* __restrict__ w0, const float* __restrict__ w1,
                                 const float* __restrict__ w2, const float* __restrict__ w3) {
    extern __shared__ float sw[];                  // [128][132] raw f32 tile
    const int bx = blockIdx.x;
    const int g  = bx >> 4;
    const int kt = (bx >> 2) & 3;
    const int q  = bx & 3;
    const int tid = threadIdx.x;
    const float* W = pick_w(w0, w1, w2, w3, g) + (size_t)kt * 128 * SDQ;

    #pragma unroll
    for (int j = 0; j < 16; j++) {
        int i = tid + 256 * j;
        int k = i >> 5, dq = (i & 31) * 4;
        *(float4*)(sw + k * 132 + dq) = *(const float4*)(W + (size_t)k * SDQ + dq);
    }
    if (bx == 0) {
        #pragma unroll
        for (int j = 0; j < 8; j++) g_avg[tid + 256 * j] = 0.f;
        if (tid == 0) g_ctr = 0u;
    }
    __syncthreads();

    if (tid < 32) {
        int k = 32 * q + tid;
        const float* r = sw + k * 132;
        float s0 = 0.f, s1 = 0.f, s2 = 0.f, s3 = 0.f;
        #pragma unroll 8
        for (int d = 0; d < SDQ; d += 4) {
            s0 = fmaf(r[d], r[d], s0);
            s1 = fmaf(r[d + 1], r[d + 1], s1);
            s2 = fmaf(r[d + 2], r[d + 2], s2);
            s3 = fmaf(r[d + 3], r[d + 3], s3);
        }
        g_csq[g * KQ + kt * 128 + k] = (s0 + s1) + (s2 + s3);
    }

    #pragma unroll
    for (int j = 0; j < 8; j++) {
        int idx = tid + 256 * j;
        int k = 32 * q + (idx >> 6);
        int o = idx & 63;
        int d0 = (o >> 4) * 32 + inv16(o & 15);
        g_w1[((size_t)(g * KQ + kt * 128 + k)) * 64 + o] =
            pk(sw[k * 132 + d0], sw[k * 132 + d0 + 1]);
    }
    #pragma unroll
    for (int j = 0; j < 8; j++) {
        int idx = tid + 256 * j;
        int d = 32 * q + (idx >> 6);
        int o = idx & 63;
        int lc = (o >> 4) * 32 + inv16(o & 15);
        g_wt[((size_t)(g * SDQ + d)) * 256 + kt * 64 + o] =
            pk(sw[lc * 132 + d], sw[(lc + 1) * 132 + d]);
    }
}

// ---------------------------------------------------------------------------
// fused main kernel: CTA = (group g, 64-token tile), 256 threads / 8 warps
// ---------------------------------------------------------------------------
__global__ __launch_bounds__(NTHR, 2)
void gsm4_fused_kernel(const float* __restrict__ x,
                       const float* __restrict__ gum,
                       float* __restrict__ out,
                       int do_perp) {
    extern __shared__ char smc[];
    const int g  = blockIdx.y;
    const int n0 = blockIdx.x * TM;
    const int b  = n0 / TQ;
    const int t0 = n0 % TQ;

    const int tid  = threadIdx.x;
    const int wid  = tid >> 5;
    const int lane = tid & 31;
    const int lg   = lane >> 2;
    const int lt   = lane & 3;
    const int wm   = wid >> 1;
    const int wq   = wid & 1;
    const int m0   = wm * 16;

    uint32_t* sP   = (uint32_t*)(smc + OFF_P);
    float* sX      = (float*)(smc + OFF_P);        // overlay (stride SXS)
    float* sCsq    = (float*)(smc + OFF_CSQ);
    float* sRs     = (float*)(smc + OFF_RS);
    float* sRinv   = (float*)(smc + OFF_RI);

    // prologue --------------------------------------------------------------
    sCsq[tid]       = (0.5f * L2E) * g_csq[g * KQ + tid];
    sCsq[tid + 256] = (0.5f * L2E) * g_csq[g * KQ + tid + 256];
    if (tid < TM) sRs[tid] = 0.f;

    {
        const float* xb = x + ((size_t)(b * 512 + g * SDQ)) * TQ + t0;
        #pragma unroll
        for (int j = 0; j < 8; j++) {
            int i = tid + NTHR * j;
            int d = i >> 4, mq = (i & 15) * 4;
            *(float4*)(sX + d * SXS + mq) = *(const float4*)(xb + (size_t)d * TQ + mq);
        }
    }
    __syncthreads();

    // A fragments (GEMM1): 8 k16-steps x 4 half2 regs -----------------------
    uint32_t af[8][4];
    #pragma unroll
    for (int s = 0; s < 8; s++) {
        int dbs = 16 * s + 2 * lt;
        af[s][0] = pk(sX[dbs * SXS + m0 + lg],           sX[(dbs + 1) * SXS + m0 + lg]);
        af[s][1] = pk(sX[dbs * SXS + m0 + lg + 8],       sX[(dbs + 1) * SXS + m0 + lg + 8]);
        af[s][2] = pk(sX[(dbs + 8) * SXS + m0 + lg],     sX[(dbs + 9) * SXS + m0 + lg]);
        af[s][3] = pk(sX[(dbs + 8) * SXS + m0 + lg + 8], sX[(dbs + 9) * SXS + m0 + lg + 8]);
    }
    __syncthreads();                                // sX dead -> sP region

    const float* gmr = gum + ((size_t)g * NTOK + n0 + m0 + lg) * KQ + wq * 32 + 2 * lt;
    const uint32_t* w1b = g_w1 + ((size_t)(g * KQ + wq * 32 + lg)) * 64 + lt * 4;
    const uint32_t* wtb = g_wt + ((size_t)(g * SDQ + wq * 64 + lg)) * 256 + lt * 4;

    // ---------------- GEMM1 + fused exp (ex2): barrier-free ----------------
    float rs0 = 0.f, rs1 = 0.f;
    for (int c = 0; c < 8; c++) {
        float acc[4][4];
        #pragma unroll
        for (int t = 0; t < 4; t++)
            #pragma unroll
            for (int e = 0; e < 4; e++) acc[t][e] = 0.f;

        #pragma unroll
        for (int kg = 0; kg < 4; kg++) {
            #pragma unroll
            for (int t = 0; t < 4; t++) {
                uint4 B = *(const uint4*)(w1b + ((size_t)(c * 64 + t * 8)) * 64 + kg * 16);
                mma_f16(acc[t], af[2 * kg][0], af[2 * kg][1], af[2 * kg][2], af[2 * kg][3], B.x, B.y);
                mma_f16(acc[t], af[2 * kg + 1][0], af[2 * kg + 1][1], af[2 * kg + 1][2], af[2 * kg + 1][3], B.z, B.w);
            }
        }
        float2 gv[8];
        {
            const float* p0 = gmr + c * 64;
            #pragma unroll
            for (int t = 0; t < 4; t++) {
                gv[t]     = *(const float2*)(p0 + 8 * t);
                gv[4 + t] = *(const float2*)(p0 + 8 * KQ + 8 * t);
            }
        }
        uint4 ua, ub;
        uint32_t* pu_a = &ua.x;
        uint32_t* pu_b = &ub.x;
        #pragma unroll
        for (int t = 0; t < 4; t++) {
            float2 cs = *(const float2*)(sCsq + c * 64 + wq * 32 + 8 * t + 2 * lt);
            float p0v = ex2(fmaf(acc[t][0], L2E, fmaf(gv[t].x,     HL2E, -cs.x)));
            float p1v = ex2(fmaf(acc[t][1], L2E, fmaf(gv[t].y,     HL2E, -cs.y)));
            float p2v = ex2(fmaf(acc[t][2], L2E, fmaf(gv[4 + t].x, HL2E, -cs.x)));
            float p3v = ex2(fmaf(acc[t][3], L2E, fmaf(gv[4 + t].y, HL2E, -cs.y)));
            rs0 += p0v + p1v;
            rs1 += p2v + p3v;
            pu_a[t] = pk(p0v, p1v);
            pu_b[t] = pk(p2v, p3v);
        }
        const int wbase = (m0 + lg) * PSW + c * 32 + wq * 16 + 4 * lt;
        *(uint4*)(sP + wbase)           = ua;
        *(uint4*)(sP + wbase + 8 * PSW) = ub;
    }
    // rowsum partials (no barrier needed before GEMM2) ----------------------
    rs0 += __shfl_xor_sync(0xffffffffu, rs0, 1);
    rs0 += __shfl_xor_sync(0xffffffffu, rs0, 2);
    rs1 += __shfl_xor_sync(0xffffffffu, rs1, 1);
    rs1 += __shfl_xor_sync(0xffffffffu, rs1, 2);
    if (lt == 0) {
        atomicAdd(&sRs[m0 + lg], rs0);
        atomicAdd(&sRs[m0 + lg + 8], rs1);
    }

    // ---------------- GEMM2: barrier-free, A = own sP rows -----------------
    float qa[8][4];
    #pragma unroll
    for (int t = 0; t < 8; t++)
        #pragma unroll
        for (int e = 0; e < 4; e++) qa[t][e] = 0.f;

    for (int c = 0; c < 8; c++) {
        #pragma unroll
        for (int g2 = 0; g2 < 2; g2++) {
            uint4 U = *(const uint4*)(sP + (m0 + lg) * PSW + (c * 2 + g2) * 16 + 4 * lt);
            uint4 V = *(const uint4*)(sP + (m0 + lg + 8) * PSW + (c * 2 + g2) * 16 + 4 * lt);
            #pragma unroll
            for (int t = 0; t < 8; t++) {
                uint4 B = *(const uint4*)(wtb + ((size_t)(t * 8)) * 256 + c * 32 + g2 * 16);
                mma_f16(qa[t], U.x, V.x, U.y, V.y, B.x, B.y);
                mma_f16(qa[t], U.z, V.z, U.w, V.w, B.z, B.w);
            }
        }
    }
    __syncthreads();                                // rowsum atomics visible
    if (tid < TM) sRinv[tid] = 1.0f / sRs[tid];
    __syncthreads();

    // avg_probs: thread per packed word column ------------------------------
    {
        int w = tid;                                // 0..255
        float s0 = 0.f, s1 = 0.f;
        #pragma unroll 8
        for (int r = 0; r < TM; r++) {
            uint32_t u = sP[r * PSW + w];
            __half2 h = *reinterpret_cast<__half2*>(&u);
            float2 f = __half22float2(h);
            float ri = sRinv[r];
            s0 = fmaf(f.x, ri, s0);
            s1 = fmaf(f.y, ri, s1);
        }
        int o = w & 15;
        int k0 = (w >> 4) * 32 + inv16(o);
        atomicAdd(&g_avg[g * KQ + k0], s0);
        atomicAdd(&g_avg[g * KQ + k0 + 1], s1);
    }
    __syncthreads();                                // sP free for staging

    // epilogue: normalize, single staging pass, coalesced STG.128 -----------
    {
        float* stage = (float*)(smc + OFF_P);       // [128 d][SXS]
        const float r1v = sRinv[m0 + lg];
        const float r2v = sRinv[m0 + lg + 8];
        #pragma unroll
        for (int t = 0; t < 8; t++) {
            int d = wq * 64 + t * 8 + 2 * lt;
            stage[d * SXS + m0 + lg]           = qa[t][0] * r1v;
            stage[(d + 1) * SXS + m0 + lg]     = qa[t][1] * r1v;
            stage[d * SXS + m0 + lg + 8]       = qa[t][2] * r2v;
            stage[(d + 1) * SXS + m0 + lg + 8] = qa[t][3] * r2v;
        }
        __syncthreads();
        float* ob = out + ((size_t)(b * 512 + g * SDQ)) * TQ + t0;
        #pragma unroll
        for (int j = 0; j < 8; j++) {
            int i = tid + NTHR * j;
            int d = i >> 4, mq = (i & 15) * 4;
            float4 v = *(const float4*)(stage + d * SXS + mq);
            *(float4*)(ob + (size_t)d * TQ + mq) = v;
        }
    }

    // ---------------- perp: last CTA reduces g_avg -------------------------
    if (do_perp) {
        __shared__ unsigned s_last;
        __shared__ float se[8];
        __threadfence();
        __syncthreads();
        if (tid == 0)
            s_last = (atomicAdd(&g_ctr, 1u) == gridDim.x * gridDim.y - 1u) ? 1u : 0u;
        __syncthreads();
        if (s_last) {
            // 64 threads per group; thread handles 8 codes
            int gg = tid >> 6;
            int tt = tid & 63;
            float acc = 0.f;
            #pragma unroll
            for (int j = 0; j < 8; j++) {
                float a = g_avg[gg * KQ + tt + 64 * j] * (1.0f / (float)NTOK);
                acc += a * logf(a + 1e-10f);
            }
            #pragma unroll
            for (int o = 16; o; o >>= 1) acc += __shfl_xor_sync(0xffffffffu, acc, o);
            if (lane == 0) se[wid] = acc;
            __syncthreads();
            if (tid == 0) {
                float p = 0.f;
                #pragma unroll
                for (int g2 = 0; g2 < NG; g2++) p += expf(-(se[2 * g2] + se[2 * g2 + 1]));
                out[QUANT_ELEMS] = p;
            }
        }
    }
}

// ---------------------------------------------------------------------------
extern "C" void kernel_launch(void* const* d_in, const int* in_sizes, int n_in,
                              void* d_out, int out_size) {
    const float* x   = (const float*)d_in[0];
    const float* w0  = (const float*)d_in[1];
    const float* w1  = (const float*)d_in[2];
    const float* w2  = (const float*)d_in[3];
    const float* w3  = (const float*)d_in[4];
    const float* gum = (const float*)d_in[5];
    float* out = (float*)d_out;

    cudaFuncSetAttribute(gsm4_prep_kernel,
                         cudaFuncAttributeMaxDynamicSharedMemorySize, 128 * 132 * 4);
    cudaFuncSetAttribute(gsm4_fused_kernel,
                         cudaFuncAttributeMaxDynamicSharedMemorySize, SMEM_BYTES);

    gsm4_prep_kernel<<<64, 256, 128 * 132 * 4>>>(w0, w1, w2, w3);

    dim3 grid(NTOK / TM, NG);
    int do_perp = (out_size > QUANT_ELEMS) ? 1 : 0;
    gsm4_fused_kernel<<<grid, NTHR, SMEM_BYTES>>>(x, gum, out, do_perp);
}

// round 12
// speedup vs baseline: 1.7057x; 1.2243x over previous
#include <cuda_runtime.h>
#include <cuda_fp16.h>
#include <cstdint>

// ---------------------------------------------------------------------------
// GumbelSoftmaxModule4 v12: v11 + fragment-major W layouts.
//   One mma B-fragment = one contiguous 512B block = one fully-coalesced
//   LDG.128 (4 L1 wavefronts instead of 8). L1tex was 81.6% of peak.
// ---------------------------------------------------------------------------

namespace {
constexpr int KQ = 512, NG = 4, SDQ = 128, BQ = 16, TQ = 2048;
constexpr int NTOK = BQ * TQ;            // 32768
constexpr int TM   = 64;                 // tokens per CTA
constexpr int NTHR = 256;                // 8 warps
constexpr int PSW  = 272;                // sP row stride (uint32 words)
constexpr int SXS  = 68;                 // X / stage row stride (f32)
constexpr int OFF_P   = 0;                          // sP: 64*272*4 = 69632
constexpr int OFF_CSQ = 69632;                      // 512 f32 (pre-scaled)
constexpr int OFF_RS  = OFF_CSQ + 2048;             // 64 f32
constexpr int OFF_RI  = OFF_RS + 256;               // 64 f32
constexpr int SMEM_BYTES = OFF_RI + 256;            // 72192 -> occ 2
constexpr int QUANT_ELEMS = BQ * 512 * TQ;
constexpr float L2E  = 1.4426950408889634f;
constexpr float HL2E = 0.7213475204444817f;
}

__device__ float g_csq[NG * KQ];
__device__ float g_avg[NG * KQ];
__device__ unsigned int g_ctr;
// fragment-major: [g][frag 0..255][128 words]; frag = 512B = one warp LDG.128
__device__ __align__(16) uint32_t g_w1f[NG * 256 * 128];
__device__ __align__(16) uint32_t g_wtf[NG * 256 * 128];

// ------------------------------ helpers ------------------------------------
__device__ __forceinline__ int inv16(int o) {
    return (((o >> 1) & 1) << 4) | ((o & 1) << 3) | (((o >> 2) & 3) << 1);
}
__device__ __forceinline__ uint32_t pk(float lo, float hi) {
    __half2 h = __floats2half2_rn(lo, hi);
    return *reinterpret_cast<uint32_t*>(&h);
}
__device__ __forceinline__ float ex2(float y) {    // 2^y via MUFU
    float r;
    asm("ex2.approx.f32 %0, %1;" : "=f"(r) : "f"(y));
    return r;
}
__device__ __forceinline__ void mma_f16(float* c,
                                        uint32_t a0, uint32_t a1, uint32_t a2, uint32_t a3,
                                        uint32_t b0, uint32_t b1) {
    asm volatile(
        "mma.sync.aligned.m16n8k16.row.col.f32.f16.f16.f32 "
        "{%0,%1,%2,%3}, {%4,%5,%6,%7}, {%8,%9}, {%0,%1,%2,%3};\n"
        : "+f"(c[0]), "+f"(c[1]), "+f"(c[2]), "+f"(c[3])
        : "r"(a0), "r"(a1), "r"(a2), "r"(a3), "r"(b0), "r"(b1));
}
__device__ __forceinline__ const float* pick_w(const float* w0, const float* w1,
                                               const float* w2, const float* w3, int g) {
    return (g == 0) ? w0 : ((g == 1) ? w1 : ((g == 2) ? w2 : w3));
}

// ---------------------------------------------------------------------------
// prep: 64 blocks = (g, kt 128-code tile, quarter q).
// Writes fragment-major g_w1f/g_wtf + csq + zero g_avg/ctr.
// ---------------------------------------------------------------------------
__global__ void gsm4_prep_kernel(const float* __restrict__ w0, const float* __restrict__ w1,
                                 const float* __restrict__ w2, const float* __restrict__ w3) {
    extern __shared__ float sw[];                  // [128][132] raw f32 tile
    const int bx = blockIdx.x;
    const int g  = bx >> 4;
    const int kt = (bx >> 2) & 3;
    const int q  = bx & 3;
    const int tid = threadIdx.x;
    const float* W = pick_w(w0, w1, w2, w3, g) + (size_t)kt * 128 * SDQ;

    #pragma unroll
    for (int j = 0; j < 16; j++) {
        int i = tid + 256 * j;
        int k = i >> 5, dq = (i & 31) * 4;
        *(float4*)(sw + k * 132 + dq) = *(const float4*)(W + (size_t)k * SDQ + dq);
    }
    if (bx == 0) {
        #pragma unroll
        for (int j = 0; j < 8; j++) g_avg[tid + 256 * j] = 0.f;
        if (tid == 0) g_ctr = 0u;
    }
    __syncthreads();

    if (tid < 32) {
        int k = 32 * q + tid;
        const float* r = sw + k * 132;
        float s0 = 0.f, s1 = 0.f, s2 = 0.f, s3 = 0.f;
        #pragma unroll 8
        for (int d = 0; d < SDQ; d += 4) {
            s0 = fmaf(r[d], r[d], s0);
            s1 = fmaf(r[d + 1], r[d + 1], s1);
            s2 = fmaf(r[d + 2], r[d + 2], s2);
            s3 = fmaf(r[d + 3], r[d + 3], s3);
        }
        g_csq[g * KQ + kt * 128 + k] = (s0 + s1) + (s2 + s3);
    }

    // g_w1f: frag flocal = c_l*32 + kg*8 + tg covers codes (2kt+c_l)*64+tg*8+lg,
    // k-words o = kg*16 + lt*4 + jj (pos32 d pairs)
    #pragma unroll
    for (int j = 0; j < 8; j++) {
        int idx = q * 2048 + tid + 256 * j;        // within this kt's 8192 words
        int flocal = idx >> 7;
        int within = idx & 127;                     // lane*4 + jj
        int lane = within >> 2, jj = within & 3;
        int lg = lane >> 2, lt = lane & 3;
        int c_l = flocal >> 5, kg = (flocal >> 3) & 3, tg = flocal & 7;
        int k_local = c_l * 64 + tg * 8 + lg;
        int o = kg * 16 + lt * 4 + jj;
        int d0 = (o >> 4) * 32 + inv16(o & 15);
        g_w1f[(size_t)g * 32768 + (size_t)(kt * 64 + flocal) * 128 + within] =
            pk(sw[k_local * 132 + d0], sw[k_local * 132 + d0 + 1]);
    }
    // g_wtf: frag flocal = c_l*32 + g2*16 + wq*8 + t covers d = wq*64+t*8+lg,
    // code-words o = c_l*32 + g2*16 + lt*4 + jj (pos32 code pairs, local to kt)
    #pragma unroll
    for (int j = 0; j < 8; j++) {
        int idx = q * 2048 + tid + 256 * j;
        int flocal = idx >> 7;
        int within = idx & 127;
        int lane = within >> 2, jj = within & 3;
        int lg = lane >> 2, lt = lane & 3;
        int c_l = flocal >> 5, g2 = (flocal >> 4) & 1, wqf = (flocal >> 3) & 1, t = flocal & 7;
        int d = wqf * 64 + t * 8 + lg;
        int o = c_l * 32 + g2 * 16 + lt * 4 + jj;
        int lc = (o >> 4) * 32 + inv16(o & 15);
        g_wtf[(size_t)g * 32768 + (size_t)(kt * 64 + flocal) * 128 + within] =
            pk(sw[lc * 132 + d], sw[(lc + 1) * 132 + d]);
    }
}

// ---------------------------------------------------------------------------
// fused main kernel: CTA = (group g, 64-token tile), 256 threads / 8 warps
// ---------------------------------------------------------------------------
__global__ __launch_bounds__(NTHR, 2)
void gsm4_fused_kernel(const float* __restrict__ x,
                       const float* __restrict__ gum,
                       float* __restrict__ out,
                       int do_perp) {
    extern __shared__ char smc[];
    const int g  = blockIdx.y;
    const int n0 = blockIdx.x * TM;
    const int b  = n0 / TQ;
    const int t0 = n0 % TQ;

    const int tid  = threadIdx.x;
    const int wid  = tid >> 5;
    const int lane = tid & 31;
    const int lg   = lane >> 2;
    const int lt   = lane & 3;
    const int wm   = wid >> 1;
    const int wq   = wid & 1;
    const int m0   = wm * 16;

    uint32_t* sP   = (uint32_t*)(smc + OFF_P);
    float* sX      = (float*)(smc + OFF_P);        // overlay (stride SXS)
    float* sCsq    = (float*)(smc + OFF_CSQ);
    float* sRs     = (float*)(smc + OFF_RS);
    float* sRinv   = (float*)(smc + OFF_RI);

    // prologue --------------------------------------------------------------
    sCsq[tid]       = (0.5f * L2E) * g_csq[g * KQ + tid];
    sCsq[tid + 256] = (0.5f * L2E) * g_csq[g * KQ + tid + 256];
    if (tid < TM) sRs[tid] = 0.f;

    {
        const float* xb = x + ((size_t)(b * 512 + g * SDQ)) * TQ + t0;
        #pragma unroll
        for (int j = 0; j < 8; j++) {
            int i = tid + NTHR * j;
            int d = i >> 4, mq = (i & 15) * 4;
            *(float4*)(sX + d * SXS + mq) = *(const float4*)(xb + (size_t)d * TQ + mq);
        }
    }
    __syncthreads();

    // A fragments (GEMM1): 8 k16-steps x 4 half2 regs -----------------------
    uint32_t af[8][4];
    #pragma unroll
    for (int s = 0; s < 8; s++) {
        int dbs = 16 * s + 2 * lt;
        af[s][0] = pk(sX[dbs * SXS + m0 + lg],           sX[(dbs + 1) * SXS + m0 + lg]);
        af[s][1] = pk(sX[dbs * SXS + m0 + lg + 8],       sX[(dbs + 1) * SXS + m0 + lg + 8]);
        af[s][2] = pk(sX[(dbs + 8) * SXS + m0 + lg],     sX[(dbs + 9) * SXS + m0 + lg]);
        af[s][3] = pk(sX[(dbs + 8) * SXS + m0 + lg + 8], sX[(dbs + 9) * SXS + m0 + lg + 8]);
    }
    __syncthreads();                                // sX dead -> sP region

    const float* gmr = gum + ((size_t)g * NTOK + n0 + m0 + lg) * KQ + wq * 32 + 2 * lt;
    // fragment-major B base pointers (coalesced LDG.128)
    const uint32_t* w1f = g_w1f + (size_t)g * 32768 + (size_t)(wq * 4) * 128 + lane * 4;
    const uint32_t* wtf = g_wtf + (size_t)g * 32768 + (size_t)(wq * 8) * 128 + lane * 4;

    // ---------------- GEMM1 + fused exp (ex2): barrier-free ----------------
    float rs0 = 0.f, rs1 = 0.f;
    for (int c = 0; c < 8; c++) {
        float acc[4][4];
        #pragma unroll
        for (int t = 0; t < 4; t++)
            #pragma unroll
            for (int e = 0; e < 4; e++) acc[t][e] = 0.f;

        #pragma unroll
        for (int kg = 0; kg < 4; kg++) {
            #pragma unroll
            for (int t = 0; t < 4; t++) {
                uint4 B = *(const uint4*)(w1f + (size_t)((c * 4 + kg) * 8 + t) * 128);
                mma_f16(acc[t], af[2 * kg][0], af[2 * kg][1], af[2 * kg][2], af[2 * kg][3], B.x, B.y);
                mma_f16(acc[t], af[2 * kg + 1][0], af[2 * kg + 1][1], af[2 * kg + 1][2], af[2 * kg + 1][3], B.z, B.w);
            }
        }
        float2 gv[8];
        {
            const float* p0 = gmr + c * 64;
            #pragma unroll
            for (int t = 0; t < 4; t++) {
                gv[t]     = *(const float2*)(p0 + 8 * t);
                gv[4 + t] = *(const float2*)(p0 + 8 * KQ + 8 * t);
            }
        }
        uint4 ua, ub;
        uint32_t* pu_a = &ua.x;
        uint32_t* pu_b = &ub.x;
        #pragma unroll
        for (int t = 0; t < 4; t++) {
            float2 cs = *(const float2*)(sCsq + c * 64 + wq * 32 + 8 * t + 2 * lt);
            float p0v = ex2(fmaf(acc[t][0], L2E, fmaf(gv[t].x,     HL2E, -cs.x)));
            float p1v = ex2(fmaf(acc[t][1], L2E, fmaf(gv[t].y,     HL2E, -cs.y)));
            float p2v = ex2(fmaf(acc[t][2], L2E, fmaf(gv[4 + t].x, HL2E, -cs.x)));
            float p3v = ex2(fmaf(acc[t][3], L2E, fmaf(gv[4 + t].y, HL2E, -cs.y)));
            rs0 += p0v + p1v;
            rs1 += p2v + p3v;
            pu_a[t] = pk(p0v, p1v);
            pu_b[t] = pk(p2v, p3v);
        }
        const int wbase = (m0 + lg) * PSW + c * 32 + wq * 16 + 4 * lt;
        *(uint4*)(sP + wbase)           = ua;
        *(uint4*)(sP + wbase + 8 * PSW) = ub;
    }
    // rowsum partials (no barrier needed before GEMM2) ----------------------
    rs0 += __shfl_xor_sync(0xffffffffu, rs0, 1);
    rs0 += __shfl_xor_sync(0xffffffffu, rs0, 2);
    rs1 += __shfl_xor_sync(0xffffffffu, rs1, 1);
    rs1 += __shfl_xor_sync(0xffffffffu, rs1, 2);
    if (lt == 0) {
        atomicAdd(&sRs[m0 + lg], rs0);
        atomicAdd(&sRs[m0 + lg + 8], rs1);
    }

    // ---------------- GEMM2: barrier-free, A = own sP rows -----------------
    float qa[8][4];
    #pragma unroll
    for (int t = 0; t < 8; t++)
        #pragma unroll
        for (int e = 0; e < 4; e++) qa[t][e] = 0.f;

    for (int c = 0; c < 8; c++) {
        #pragma unroll
        for (int g2 = 0; g2 < 2; g2++) {
            uint4 U = *(const uint4*)(sP + (m0 + lg) * PSW + (c * 2 + g2) * 16 + 4 * lt);
            uint4 V = *(const uint4*)(sP + (m0 + lg + 8) * PSW + (c * 2 + g2) * 16 + 4 * lt);
            #pragma unroll
            for (int t = 0; t < 8; t++) {
                uint4 B = *(const uint4*)(wtf + (size_t)((c * 2 + g2) * 16 + t) * 128);
                mma_f16(qa[t], U.x, V.x, U.y, V.y, B.x, B.y);
                mma_f16(qa[t], U.z, V.z, U.w, V.w, B.z, B.w);
            }
        }
    }
    __syncthreads();                                // rowsum atomics visible
    if (tid < TM) sRinv[tid] = 1.0f / sRs[tid];
    __syncthreads();

    // avg_probs: thread per packed word column ------------------------------
    {
        int w = tid;                                // 0..255
        float s0 = 0.f, s1 = 0.f;
        #pragma unroll 8
        for (int r = 0; r < TM; r++) {
            uint32_t u = sP[r * PSW + w];
            __half2 h = *reinterpret_cast<__half2*>(&u);
            float2 f = __half22float2(h);
            float ri = sRinv[r];
            s0 = fmaf(f.x, ri, s0);
            s1 = fmaf(f.y, ri, s1);
        }
        int o = w & 15;
        int k0 = (w >> 4) * 32 + inv16(o);
        atomicAdd(&g_avg[g * KQ + k0], s0);
        atomicAdd(&g_avg[g * KQ + k0 + 1], s1);
    }
    __syncthreads();                                // sP free for staging

    // epilogue: normalize, single staging pass, coalesced STG.128 -----------
    {
        float* stage = (float*)(smc + OFF_P);       // [128 d][SXS]
        const float r1v = sRinv[m0 + lg];
        const float r2v = sRinv[m0 + lg + 8];
        #pragma unroll
        for (int t = 0; t < 8; t++) {
            int d = wq * 64 + t * 8 + 2 * lt;
            stage[d * SXS + m0 + lg]           = qa[t][0] * r1v;
            stage[(d + 1) * SXS + m0 + lg]     = qa[t][1] * r1v;
            stage[d * SXS + m0 + lg + 8]       = qa[t][2] * r2v;
            stage[(d + 1) * SXS + m0 + lg + 8] = qa[t][3] * r2v;
        }
        __syncthreads();
        float* ob = out + ((size_t)(b * 512 + g * SDQ)) * TQ + t0;
        #pragma unroll
        for (int j = 0; j < 8; j++) {
            int i = tid + NTHR * j;
            int d = i >> 4, mq = (i & 15) * 4;
            float4 v = *(const float4*)(stage + d * SXS + mq);
            *(float4*)(ob + (size_t)d * TQ + mq) = v;
        }
    }

    // ---------------- perp: last CTA reduces g_avg -------------------------
    if (do_perp) {
        __shared__ unsigned s_last;
        __shared__ float se[8];
        __threadfence();
        __syncthreads();
        if (tid == 0)
            s_last = (atomicAdd(&g_ctr, 1u) == gridDim.x * gridDim.y - 1u) ? 1u : 0u;
        __syncthreads();
        if (s_last) {
            int gg = tid >> 6;
            int tt = tid & 63;
            float acc = 0.f;
            #pragma unroll
            for (int j = 0; j < 8; j++) {
                float a = g_avg[gg * KQ + tt + 64 * j] * (1.0f / (float)NTOK);
                acc += a * logf(a + 1e-10f);
            }
            #pragma unroll
            for (int o = 16; o; o >>= 1) acc += __shfl_xor_sync(0xffffffffu, acc, o);
            if (lane == 0) se[wid] = acc;
            __syncthreads();
            if (tid == 0) {
                float p = 0.f;
                #pragma unroll
                for (int g2 = 0; g2 < NG; g2++) p += expf(-(se[2 * g2] + se[2 * g2 + 1]));
                out[QUANT_ELEMS] = p;
            }
        }
    }
}

// ---------------------------------------------------------------------------
extern "C" void kernel_launch(void* const* d_in, const int* in_sizes, int n_in,
                              void* d_out, int out_size) {
    const float* x   = (const float*)d_in[0];
    const float* w0  = (const float*)d_in[1];
    const float* w1  = (const float*)d_in[2];
    const float* w2  = (const float*)d_in[3];
    const float* w3  = (const float*)d_in[4];
    const float* gum = (const float*)d_in[5];
    float* out = (float*)d_out;

    cudaFuncSetAttribute(gsm4_prep_kernel,
                         cudaFuncAttributeMaxDynamicSharedMemorySize, 128 * 132 * 4);
    cudaFuncSetAttribute(gsm4_fused_kernel,
                         cudaFuncAttributeMaxDynamicSharedMemorySize, SMEM_BYTES);

    gsm4_prep_kernel<<<64, 256, 128 * 132 * 4>>>(w0, w1, w2, w3);

    dim3 grid(NTOK / TM, NG);
    int do_perp = (out_size > QUANT_ELEMS) ? 1 : 0;
    gsm4_fused_kernel<<<grid, NTHR, SMEM_BYTES>>>(x, gum, out, do_perp);
}

// round 13
// speedup vs baseline: 1.7542x; 1.0284x over previous
#include <cuda_runtime.h>
#include <cuda_fp16.h>
#include <cstdint>

// ---------------------------------------------------------------------------
// GumbelSoftmaxModule4 v13: v12 + linear code labeling.
//   Thread's 8 probs/chunk = 8 consecutive codes -> gumbel via float4 (32B
//   contiguous per lane, half the wavefronts); csq linear; sP word w holds
//   codes (2w, 2w+1) so all inv16 mapping disappears.
// ---------------------------------------------------------------------------

namespace {
constexpr int KQ = 512, NG = 4, SDQ = 128, BQ = 16, TQ = 2048;
constexpr int NTOK = BQ * TQ;            // 32768
constexpr int TM   = 64;                 // tokens per CTA
constexpr int NTHR = 256;                // 8 warps
constexpr int PSW  = 272;                // sP row stride (uint32 words)
constexpr int SXS  = 68;                 // X / stage row stride (f32)
constexpr int OFF_P   = 0;                          // sP: 64*272*4 = 69632
constexpr int OFF_CSQ = 69632;                      // 512 f32 (pre-scaled)
constexpr int OFF_RS  = OFF_CSQ + 2048;             // 64 f32
constexpr int OFF_RI  = OFF_RS + 256;               // 64 f32
constexpr int SMEM_BYTES = OFF_RI + 256;            // 72192 -> occ 2
constexpr int QUANT_ELEMS = BQ * 512 * TQ;
constexpr float L2E  = 1.4426950408889634f;
constexpr float HL2E = 0.7213475204444817f;
}

__device__ float g_csq[NG * KQ];
__device__ float g_avg[NG * KQ];
__device__ unsigned int g_ctr;
// fragment-major: [g][frag 0..255][128 words]; frag = 512B = one warp LDG.128
__device__ __align__(16) uint32_t g_w1f[NG * 256 * 128];
__device__ __align__(16) uint32_t g_wtf[NG * 256 * 128];

// ------------------------------ helpers ------------------------------------
__device__ __forceinline__ int inv16(int o) {      // GEMM1 d-interleave only
    return (((o >> 1) & 1) << 4) | ((o & 1) << 3) | (((o >> 2) & 3) << 1);
}
__device__ __forceinline__ uint32_t pk(float lo, float hi) {
    __half2 h = __floats2half2_rn(lo, hi);
    return *reinterpret_cast<uint32_t*>(&h);
}
__device__ __forceinline__ float ex2(float y) {    // 2^y via MUFU
    float r;
    asm("ex2.approx.f32 %0, %1;" : "=f"(r) : "f"(y));
    return r;
}
__device__ __forceinline__ void mma_f16(float* c,
                                        uint32_t a0, uint32_t a1, uint32_t a2, uint32_t a3,
                                        uint32_t b0, uint32_t b1) {
    asm volatile(
        "mma.sync.aligned.m16n8k16.row.col.f32.f16.f16.f32 "
        "{%0,%1,%2,%3}, {%4,%5,%6,%7}, {%8,%9}, {%0,%1,%2,%3};\n"
        : "+f"(c[0]), "+f"(c[1]), "+f"(c[2]), "+f"(c[3])
        : "r"(a0), "r"(a1), "r"(a2), "r"(a3), "r"(b0), "r"(b1));
}
__device__ __forceinline__ const float* pick_w(const float* w0, const float* w1,
                                               const float* w2, const float* w3, int g) {
    return (g == 0) ? w0 : ((g == 1) ? w1 : ((g == 2) ? w2 : w3));
}

// ---------------------------------------------------------------------------
// prep: 64 blocks = (g, kt 128-code tile, quarter q).
// ---------------------------------------------------------------------------
__global__ void gsm4_prep_kernel(const float* __restrict__ w0, const float* __restrict__ w1,
                                 const float* __restrict__ w2, const float* __restrict__ w3) {
    extern __shared__ float sw[];                  // [128][132] raw f32 tile
    const int bx = blockIdx.x;
    const int g  = bx >> 4;
    const int kt = (bx >> 2) & 3;
    const int q  = bx & 3;
    const int tid = threadIdx.x;
    const float* W = pick_w(w0, w1, w2, w3, g) + (size_t)kt * 128 * SDQ;

    #pragma unroll
    for (int j = 0; j < 16; j++) {
        int i = tid + 256 * j;
        int k = i >> 5, dq = (i & 31) * 4;
        *(float4*)(sw + k * 132 + dq) = *(const float4*)(W + (size_t)k * SDQ + dq);
    }
    if (bx == 0) {
        #pragma unroll
        for (int j = 0; j < 8; j++) g_avg[tid + 256 * j] = 0.f;
        if (tid == 0) g_ctr = 0u;
    }
    __syncthreads();

    if (tid < 32) {
        int k = 32 * q + tid;
        const float* r = sw + k * 132;
        float s0 = 0.f, s1 = 0.f, s2 = 0.f, s3 = 0.f;
        #pragma unroll 8
        for (int d = 0; d < SDQ; d += 4) {
            s0 = fmaf(r[d], r[d], s0);
            s1 = fmaf(r[d + 1], r[d + 1], s1);
            s2 = fmaf(r[d + 2], r[d + 2], s2);
            s3 = fmaf(r[d + 3], r[d + 3], s3);
        }
        g_csq[g * KQ + kt * 128 + k] = (s0 + s1) + (s2 + s3);
    }

    // g_w1f: frag flocal = c_l*32 + kg*8 + tg; lane's n-pos = lg.
    // code label: k_local = c_l*64 + (tg>>2)*32 + (lg>>1)*8 + (tg&3)*2 + (lg&1)
    #pragma unroll
    for (int j = 0; j < 8; j++) {
        int idx = q * 2048 + tid + 256 * j;
        int flocal = idx >> 7;
        int within = idx & 127;
        int lane = within >> 2, jj = within & 3;
        int lg = lane >> 2, lt = lane & 3;
        int c_l = flocal >> 5, kg = (flocal >> 3) & 3, tg = flocal & 7;
        int k_local = c_l * 64 + (tg >> 2) * 32 + (lg >> 1) * 8 + (tg & 3) * 2 + (lg & 1);
        int o = kg * 16 + lt * 4 + jj;
        int d0 = (o >> 4) * 32 + inv16(o & 15);
        g_w1f[(size_t)g * 32768 + (size_t)(kt * 64 + flocal) * 128 + within] =
            pk(sw[k_local * 132 + d0], sw[k_local * 132 + d0 + 1]);
    }
    // g_wtf: frag flocal = c_l*32 + g2*16 + wqf*8 + t; word o -> codes (2o,2o+1)
    #pragma unroll
    for (int j = 0; j < 8; j++) {
        int idx = q * 2048 + tid + 256 * j;
        int flocal = idx >> 7;
        int within = idx & 127;
        int lane = within >> 2, jj = within & 3;
        int lg = lane >> 2, lt = lane & 3;
        int c_l = flocal >> 5, g2 = (flocal >> 4) & 1, wqf = (flocal >> 3) & 1, t = flocal & 7;
        int d = wqf * 64 + t * 8 + lg;
        int o = c_l * 32 + g2 * 16 + lt * 4 + jj;
        g_wtf[(size_t)g * 32768 + (size_t)(kt * 64 + flocal) * 128 + within] =
            pk(sw[(2 * o) * 132 + d], sw[(2 * o + 1) * 132 + d]);
    }
}

// ---------------------------------------------------------------------------
// fused main kernel: CTA = (group g, 64-token tile), 256 threads / 8 warps
// ---------------------------------------------------------------------------
__global__ __launch_bounds__(NTHR, 2)
void gsm4_fused_kernel(const float* __restrict__ x,
                       const float* __restrict__ gum,
                       float* __restrict__ out,
                       int do_perp) {
    extern __shared__ char smc[];
    const int g  = blockIdx.y;
    const int n0 = blockIdx.x * TM;
    const int b  = n0 / TQ;
    const int t0 = n0 % TQ;

    const int tid  = threadIdx.x;
    const int wid  = tid >> 5;
    const int lane = tid & 31;
    const int lg   = lane >> 2;
    const int lt   = lane & 3;
    const int wm   = wid >> 1;
    const int wq   = wid & 1;
    const int m0   = wm * 16;

    uint32_t* sP   = (uint32_t*)(smc + OFF_P);
    float* sX      = (float*)(smc + OFF_P);        // overlay (stride SXS)
    float* sCsq    = (float*)(smc + OFF_CSQ);
    float* sRs     = (float*)(smc + OFF_RS);
    float* sRinv   = (float*)(smc + OFF_RI);

    // prologue --------------------------------------------------------------
    sCsq[tid]       = (0.5f * L2E) * g_csq[g * KQ + tid];
    sCsq[tid + 256] = (0.5f * L2E) * g_csq[g * KQ + tid + 256];
    if (tid < TM) sRs[tid] = 0.f;

    {
        const float* xb = x + ((size_t)(b * 512 + g * SDQ)) * TQ + t0;
        #pragma unroll
        for (int j = 0; j < 8; j++) {
            int i = tid + NTHR * j;
            int d = i >> 4, mq = (i & 15) * 4;
            *(float4*)(sX + d * SXS + mq) = *(const float4*)(xb + (size_t)d * TQ + mq);
        }
    }
    __syncthreads();

    // A fragments (GEMM1): 8 k16-steps x 4 half2 regs -----------------------
    uint32_t af[8][4];
    #pragma unroll
    for (int s = 0; s < 8; s++) {
        int dbs = 16 * s + 2 * lt;
        af[s][0] = pk(sX[dbs * SXS + m0 + lg],           sX[(dbs + 1) * SXS + m0 + lg]);
        af[s][1] = pk(sX[dbs * SXS + m0 + lg + 8],       sX[(dbs + 1) * SXS + m0 + lg + 8]);
        af[s][2] = pk(sX[(dbs + 8) * SXS + m0 + lg],     sX[(dbs + 9) * SXS + m0 + lg]);
        af[s][3] = pk(sX[(dbs + 8) * SXS + m0 + lg + 8], sX[(dbs + 9) * SXS + m0 + lg + 8]);
    }
    __syncthreads();                                // sX dead -> sP region

    // contiguous 32B gumbel base per thread (codes wq*32+lt*8 .. +7)
    const float* gmr = gum + ((size_t)g * NTOK + n0 + m0 + lg) * KQ + wq * 32 + lt * 8;
    const uint32_t* w1f = g_w1f + (size_t)g * 32768 + (size_t)(wq * 4) * 128 + lane * 4;
    const uint32_t* wtf = g_wtf + (size_t)g * 32768 + (size_t)(wq * 8) * 128 + lane * 4;

    // ---------------- GEMM1 + fused exp (ex2): barrier-free ----------------
    float rs0 = 0.f, rs1 = 0.f;
    for (int c = 0; c < 8; c++) {
        // loads first (hidden behind the mma block)
        float4 csa = *(const float4*)(sCsq + c * 64 + wq * 32 + lt * 8);
        float4 csb = *(const float4*)(sCsq + c * 64 + wq * 32 + lt * 8 + 4);
        const float* pA = gmr + c * 64;
        float4 ga0 = *(const float4*)(pA);
        float4 ga1 = *(const float4*)(pA + 4);
        float4 gb0 = *(const float4*)(pA + 8 * KQ);
        float4 gb1 = *(const float4*)(pA + 8 * KQ + 4);

        float acc[4][4];
        #pragma unroll
        for (int t = 0; t < 4; t++)
            #pragma unroll
            for (int e = 0; e < 4; e++) acc[t][e] = 0.f;

        #pragma unroll
        for (int kg = 0; kg < 4; kg++) {
            #pragma unroll
            for (int t = 0; t < 4; t++) {
                uint4 B = *(const uint4*)(w1f + (size_t)((c * 4 + kg) * 8 + t) * 128);
                mma_f16(acc[t], af[2 * kg][0], af[2 * kg][1], af[2 * kg][2], af[2 * kg][3], B.x, B.y);
                mma_f16(acc[t], af[2 * kg + 1][0], af[2 * kg + 1][1], af[2 * kg + 1][2], af[2 * kg + 1][3], B.z, B.w);
            }
        }
        const float csv[8] = {csa.x, csa.y, csa.z, csa.w, csb.x, csb.y, csb.z, csb.w};
        const float gav[8] = {ga0.x, ga0.y, ga0.z, ga0.w, ga1.x, ga1.y, ga1.z, ga1.w};
        const float gbv[8] = {gb0.x, gb0.y, gb0.z, gb0.w, gb1.x, gb1.y, gb1.z, gb1.w};
        uint4 ua, ub;
        uint32_t* pu_a = &ua.x;
        uint32_t* pu_b = &ub.x;
        #pragma unroll
        for (int t = 0; t < 4; t++) {
            float p0v = ex2(fmaf(acc[t][0], L2E, fmaf(gav[2 * t],     HL2E, -csv[2 * t])));
            float p1v = ex2(fmaf(acc[t][1], L2E, fmaf(gav[2 * t + 1], HL2E, -csv[2 * t + 1])));
            float p2v = ex2(fmaf(acc[t][2], L2E, fmaf(gbv[2 * t],     HL2E, -csv[2 * t])));
            float p3v = ex2(fmaf(acc[t][3], L2E, fmaf(gbv[2 * t + 1], HL2E, -csv[2 * t + 1])));
            rs0 += p0v + p1v;
            rs1 += p2v + p3v;
            pu_a[t] = pk(p0v, p1v);
            pu_b[t] = pk(p2v, p3v);
        }
        const int wbase = (m0 + lg) * PSW + c * 32 + wq * 16 + 4 * lt;
        *(uint4*)(sP + wbase)           = ua;
        *(uint4*)(sP + wbase + 8 * PSW) = ub;
    }
    // rowsum partials (no barrier needed before GEMM2) ----------------------
    rs0 += __shfl_xor_sync(0xffffffffu, rs0, 1);
    rs0 += __shfl_xor_sync(0xffffffffu, rs0, 2);
    rs1 += __shfl_xor_sync(0xffffffffu, rs1, 1);
    rs1 += __shfl_xor_sync(0xffffffffu, rs1, 2);
    if (lt == 0) {
        atomicAdd(&sRs[m0 + lg], rs0);
        atomicAdd(&sRs[m0 + lg + 8], rs1);
    }

    // ---------------- GEMM2: barrier-free, A = own sP rows -----------------
    float qa[8][4];
    #pragma unroll
    for (int t = 0; t < 8; t++)
        #pragma unroll
        for (int e = 0; e < 4; e++) qa[t][e] = 0.f;

    for (int c = 0; c < 8; c++) {
        #pragma unroll
        for (int g2 = 0; g2 < 2; g2++) {
            uint4 U = *(const uint4*)(sP + (m0 + lg) * PSW + (c * 2 + g2) * 16 + 4 * lt);
            uint4 V = *(const uint4*)(sP + (m0 + lg + 8) * PSW + (c * 2 + g2) * 16 + 4 * lt);
            #pragma unroll
            for (int t = 0; t < 8; t++) {
                uint4 B = *(const uint4*)(wtf + (size_t)((c * 2 + g2) * 16 + t) * 128);
                mma_f16(qa[t], U.x, V.x, U.y, V.y, B.x, B.y);
                mma_f16(qa[t], U.z, V.z, U.w, V.w, B.z, B.w);
            }
        }
    }
    __syncthreads();                                // rowsum atomics visible
    if (tid < TM) sRinv[tid] = 1.0f / sRs[tid];
    __syncthreads();

    // avg_probs: thread tid owns codes (2*tid, 2*tid+1) ---------------------
    {
        float s0 = 0.f, s1 = 0.f;
        #pragma unroll 8
        for (int r = 0; r < TM; r++) {
            uint32_t u = sP[r * PSW + tid];
            __half2 h = *reinterpret_cast<__half2*>(&u);
            float2 f = __half22float2(h);
            float ri = sRinv[r];
            s0 = fmaf(f.x, ri, s0);
            s1 = fmaf(f.y, ri, s1);
        }
        atomicAdd(&g_avg[g * KQ + 2 * tid], s0);
        atomicAdd(&g_avg[g * KQ + 2 * tid + 1], s1);
    }
    __syncthreads();                                // sP free for staging

    // epilogue: normalize, single staging pass, coalesced STG.128 -----------
    {
        float* stage = (float*)(smc + OFF_P);       // [128 d][SXS]
        const float r1v = sRinv[m0 + lg];
        const float r2v = sRinv[m0 + lg + 8];
        #pragma unroll
        for (int t = 0; t < 8; t++) {
            int d = wq * 64 + t * 8 + 2 * lt;
            stage[d * SXS + m0 + lg]           = qa[t][0] * r1v;
            stage[(d + 1) * SXS + m0 + lg]     = qa[t][1] * r1v;
            stage[d * SXS + m0 + lg + 8]       = qa[t][2] * r2v;
            stage[(d + 1) * SXS + m0 + lg + 8] = qa[t][3] * r2v;
        }
        __syncthreads();
        float* ob = out + ((size_t)(b * 512 + g * SDQ)) * TQ + t0;
        #pragma unroll
        for (int j = 0; j < 8; j++) {
            int i = tid + NTHR * j;
            int d = i >> 4, mq = (i & 15) * 4;
            float4 v = *(const float4*)(stage + d * SXS + mq);
            *(float4*)(ob + (size_t)d * TQ + mq) = v;
        }
    }

    // ---------------- perp: last CTA reduces g_avg -------------------------
    if (do_perp) {
        __shared__ unsigned s_last;
        __shared__ float se[8];
        __threadfence();
        __syncthreads();
        if (tid == 0)
            s_last = (atomicAdd(&g_ctr, 1u) == gridDim.x * gridDim.y - 1u) ? 1u : 0u;
        __syncthreads();
        if (s_last) {
            int gg = tid >> 6;
            int tt = tid & 63;
            float acc = 0.f;
            #pragma unroll
            for (int j = 0; j < 8; j++) {
                float a = g_avg[gg * KQ + tt + 64 * j] * (1.0f / (float)NTOK);
                acc += a * logf(a + 1e-10f);
            }
            #pragma unroll
            for (int o = 16; o; o >>= 1) acc += __shfl_xor_sync(0xffffffffu, acc, o);
            if (lane == 0) se[wid] = acc;
            __syncthreads();
            if (tid == 0) {
                float p = 0.f;
                #pragma unroll
                for (int g2 = 0; g2 < NG; g2++) p += expf(-(se[2 * g2] + se[2 * g2 + 1]));
                out[QUANT_ELEMS] = p;
            }
        }
    }
}

// ---------------------------------------------------------------------------
extern "C" void kernel_launch(void* const* d_in, const int* in_sizes, int n_in,
                              void* d_out, int out_size) {
    const float* x   = (const float*)d_in[0];
    const float* w0  = (const float*)d_in[1];
    const float* w1  = (const float*)d_in[2];
    const float* w2  = (const float*)d_in[3];
    const float* w3  = (const float*)d_in[4];
    const float* gum = (const float*)d_in[5];
    float* out = (float*)d_out;

    cudaFuncSetAttribute(gsm4_prep_kernel,
                         cudaFuncAttributeMaxDynamicSharedMemorySize, 128 * 132 * 4);
    cudaFuncSetAttribute(gsm4_fused_kernel,
                         cudaFuncAttributeMaxDynamicSharedMemorySize, SMEM_BYTES);

    gsm4_prep_kernel<<<64, 256, 128 * 132 * 4>>>(w0, w1, w2, w3);

    dim3 grid(NTOK / TM, NG);
    int do_perp = (out_size > QUANT_ELEMS) ? 1 : 0;
    gsm4_fused_kernel<<<grid, NTHR, SMEM_BYTES>>>(x, gum, out, do_perp);
}

// round 14
// speedup vs baseline: 1.8678x; 1.0647x over previous
#include <cuda_runtime.h>
#include <cuda_fp16.h>
#include <cstdint>

// ---------------------------------------------------------------------------
// GumbelSoftmaxModule4 v14: v13 + GEMM2 warps widened in m (32 rows x 32 d).
//   B duplication across m halves: GEMM2 B fragments 128 -> 64 per warp
//   (-2048 L1 wavefronts/CTA) at the cost of one barrier + 2x sP A-reads.
// ---------------------------------------------------------------------------

namespace {
constexpr int KQ = 512, NG = 4, SDQ = 128, BQ = 16, TQ = 2048;
constexpr int NTOK = BQ * TQ;            // 32768
constexpr int TM   = 64;                 // tokens per CTA
constexpr int NTHR = 256;                // 8 warps
constexpr int PSW  = 272;                // sP row stride (uint32 words)
constexpr int SXS  = 68;                 // X / stage row stride (f32)
constexpr int OFF_P   = 0;                          // sP: 64*272*4 = 69632
constexpr int OFF_CSQ = 69632;                      // 512 f32 (pre-scaled)
constexpr int OFF_RS  = OFF_CSQ + 2048;             // 64 f32
constexpr int OFF_RI  = OFF_RS + 256;               // 64 f32
constexpr int SMEM_BYTES = OFF_RI + 256;            // 72192 -> occ 2
constexpr int QUANT_ELEMS = BQ * 512 * TQ;
constexpr float L2E  = 1.4426950408889634f;
constexpr float HL2E = 0.7213475204444817f;
}

__device__ float g_csq[NG * KQ];
__device__ float g_avg[NG * KQ];
__device__ unsigned int g_ctr;
// fragment-major: [g][frag 0..255][128 words]; frag = 512B = one warp LDG.128
__device__ __align__(16) uint32_t g_w1f[NG * 256 * 128];
__device__ __align__(16) uint32_t g_wtf[NG * 256 * 128];

// ------------------------------ helpers ------------------------------------
__device__ __forceinline__ int inv16(int o) {      // GEMM1 d-interleave only
    return (((o >> 1) & 1) << 4) | ((o & 1) << 3) | (((o >> 2) & 3) << 1);
}
__device__ __forceinline__ uint32_t pk(float lo, float hi) {
    __half2 h = __floats2half2_rn(lo, hi);
    return *reinterpret_cast<uint32_t*>(&h);
}
__device__ __forceinline__ float ex2(float y) {    // 2^y via MUFU
    float r;
    asm("ex2.approx.f32 %0, %1;" : "=f"(r) : "f"(y));
    return r;
}
__device__ __forceinline__ void mma_f16(float* c,
                                        uint32_t a0, uint32_t a1, uint32_t a2, uint32_t a3,
                                        uint32_t b0, uint32_t b1) {
    asm volatile(
        "mma.sync.aligned.m16n8k16.row.col.f32.f16.f16.f32 "
        "{%0,%1,%2,%3}, {%4,%5,%6,%7}, {%8,%9}, {%0,%1,%2,%3};\n"
        : "+f"(c[0]), "+f"(c[1]), "+f"(c[2]), "+f"(c[3])
        : "r"(a0), "r"(a1), "r"(a2), "r"(a3), "r"(b0), "r"(b1));
}
__device__ __forceinline__ const float* pick_w(const float* w0, const float* w1,
                                               const float* w2, const float* w3, int g) {
    return (g == 0) ? w0 : ((g == 1) ? w1 : ((g == 2) ? w2 : w3));
}

// ---------------------------------------------------------------------------
// prep: 64 blocks = (g, kt 128-code tile, quarter q).  (unchanged from v13)
// ---------------------------------------------------------------------------
__global__ void gsm4_prep_kernel(const float* __restrict__ w0, const float* __restrict__ w1,
                                 const float* __restrict__ w2, const float* __restrict__ w3) {
    extern __shared__ float sw[];                  // [128][132] raw f32 tile
    const int bx = blockIdx.x;
    const int g  = bx >> 4;
    const int kt = (bx >> 2) & 3;
    const int q  = bx & 3;
    const int tid = threadIdx.x;
    const float* W = pick_w(w0, w1, w2, w3, g) + (size_t)kt * 128 * SDQ;

    #pragma unroll
    for (int j = 0; j < 16; j++) {
        int i = tid + 256 * j;
        int k = i >> 5, dq = (i & 31) * 4;
        *(float4*)(sw + k * 132 + dq) = *(const float4*)(W + (size_t)k * SDQ + dq);
    }
    if (bx == 0) {
        #pragma unroll
        for (int j = 0; j < 8; j++) g_avg[tid + 256 * j] = 0.f;
        if (tid == 0) g_ctr = 0u;
    }
    __syncthreads();

    if (tid < 32) {
        int k = 32 * q + tid;
        const float* r = sw + k * 132;
        float s0 = 0.f, s1 = 0.f, s2 = 0.f, s3 = 0.f;
        #pragma unroll 8
        for (int d = 0; d < SDQ; d += 4) {
            s0 = fmaf(r[d], r[d], s0);
            s1 = fmaf(r[d + 1], r[d + 1], s1);
            s2 = fmaf(r[d + 2], r[d + 2], s2);
            s3 = fmaf(r[d + 3], r[d + 3], s3);
        }
        g_csq[g * KQ + kt * 128 + k] = (s0 + s1) + (s2 + s3);
    }

    // g_w1f: frag flocal = c_l*32 + kg*8 + tg; lane's n-pos = lg.
    #pragma unroll
    for (int j = 0; j < 8; j++) {
        int idx = q * 2048 + tid + 256 * j;
        int flocal = idx >> 7;
        int within = idx & 127;
        int lane = within >> 2, jj = within & 3;
        int lg = lane >> 2, lt = lane & 3;
        int c_l = flocal >> 5, kg = (flocal >> 3) & 3, tg = flocal & 7;
        int k_local = c_l * 64 + (tg >> 2) * 32 + (lg >> 1) * 8 + (tg & 3) * 2 + (lg & 1);
        int o = kg * 16 + lt * 4 + jj;
        int d0 = (o >> 4) * 32 + inv16(o & 15);
        g_w1f[(size_t)g * 32768 + (size_t)(kt * 64 + flocal) * 128 + within] =
            pk(sw[k_local * 132 + d0], sw[k_local * 132 + d0 + 1]);
    }
    // g_wtf: frag flocal = c_l*32 + g2*16 + wqf*8 + t; word o -> codes (2o,2o+1)
    #pragma unroll
    for (int j = 0; j < 8; j++) {
        int idx = q * 2048 + tid + 256 * j;
        int flocal = idx >> 7;
        int within = idx & 127;
        int lane = within >> 2, jj = within & 3;
        int lg = lane >> 2, lt = lane & 3;
        int c_l = flocal >> 5, g2 = (flocal >> 4) & 1, wqf = (flocal >> 3) & 1, t = flocal & 7;
        int d = wqf * 64 + t * 8 + lg;
        int o = c_l * 32 + g2 * 16 + lt * 4 + jj;
        g_wtf[(size_t)g * 32768 + (size_t)(kt * 64 + flocal) * 128 + within] =
            pk(sw[(2 * o) * 132 + d], sw[(2 * o + 1) * 132 + d]);
    }
}

// ---------------------------------------------------------------------------
// fused main kernel: CTA = (group g, 64-token tile), 256 threads / 8 warps
// GEMM1 warp: (wm = wid>>1, wq = wid&1)  -> 16 rows x 32 codes/chunk
// GEMM2 warp: (wm2 = wid>>2, wq2 = wid&3) -> 32 rows x 32 d
// ---------------------------------------------------------------------------
__global__ __launch_bounds__(NTHR, 2)
void gsm4_fused_kernel(const float* __restrict__ x,
                       const float* __restrict__ gum,
                       float* __restrict__ out,
                       int do_perp) {
    extern __shared__ char smc[];
    const int g  = blockIdx.y;
    const int n0 = blockIdx.x * TM;
    const int b  = n0 / TQ;
    const int t0 = n0 % TQ;

    const int tid  = threadIdx.x;
    const int wid  = tid >> 5;
    const int lane = tid & 31;
    const int lg   = lane >> 2;
    const int lt   = lane & 3;
    const int wm   = wid >> 1;
    const int wq   = wid & 1;
    const int m0   = wm * 16;
    const int wm2  = wid >> 2;
    const int wq2  = wid & 3;
    const int M2   = wm2 * 32;

    uint32_t* sP   = (uint32_t*)(smc + OFF_P);
    float* sX      = (float*)(smc + OFF_P);        // overlay (stride SXS)
    float* sCsq    = (float*)(smc + OFF_CSQ);
    float* sRs     = (float*)(smc + OFF_RS);
    float* sRinv   = (float*)(smc + OFF_RI);

    // prologue --------------------------------------------------------------
    sCsq[tid]       = (0.5f * L2E) * g_csq[g * KQ + tid];
    sCsq[tid + 256] = (0.5f * L2E) * g_csq[g * KQ + tid + 256];
    if (tid < TM) sRs[tid] = 0.f;

    {
        const float* xb = x + ((size_t)(b * 512 + g * SDQ)) * TQ + t0;
        #pragma unroll
        for (int j = 0; j < 8; j++) {
            int i = tid + NTHR * j;
            int d = i >> 4, mq = (i & 15) * 4;
            *(float4*)(sX + d * SXS + mq) = *(const float4*)(xb + (size_t)d * TQ + mq);
        }
    }
    __syncthreads();

    // A fragments (GEMM1): 8 k16-steps x 4 half2 regs -----------------------
    uint32_t af[8][4];
    #pragma unroll
    for (int s = 0; s < 8; s++) {
        int dbs = 16 * s + 2 * lt;
        af[s][0] = pk(sX[dbs * SXS + m0 + lg],           sX[(dbs + 1) * SXS + m0 + lg]);
        af[s][1] = pk(sX[dbs * SXS + m0 + lg + 8],       sX[(dbs + 1) * SXS + m0 + lg + 8]);
        af[s][2] = pk(sX[(dbs + 8) * SXS + m0 + lg],     sX[(dbs + 9) * SXS + m0 + lg]);
        af[s][3] = pk(sX[(dbs + 8) * SXS + m0 + lg + 8], sX[(dbs + 9) * SXS + m0 + lg + 8]);
    }
    __syncthreads();                                // sX dead -> sP region

    // contiguous 32B gumbel base per thread (codes wq*32+lt*8 .. +7)
    const float* gmr = gum + ((size_t)g * NTOK + n0 + m0 + lg) * KQ + wq * 32 + lt * 8;
    const uint32_t* w1f = g_w1f + (size_t)g * 32768 + (size_t)(wq * 4) * 128 + lane * 4;
    const uint32_t* wtf = g_wtf + (size_t)g * 32768 + (size_t)(wq2 * 4) * 128 + lane * 4;

    // ---------------- GEMM1 + fused exp (ex2): barrier-free ----------------
    float rs0 = 0.f, rs1 = 0.f;
    for (int c = 0; c < 8; c++) {
        float4 csa = *(const float4*)(sCsq + c * 64 + wq * 32 + lt * 8);
        float4 csb = *(const float4*)(sCsq + c * 64 + wq * 32 + lt * 8 + 4);
        const float* pA = gmr + c * 64;
        float4 ga0 = *(const float4*)(pA);
        float4 ga1 = *(const float4*)(pA + 4);
        float4 gb0 = *(const float4*)(pA + 8 * KQ);
        float4 gb1 = *(const float4*)(pA + 8 * KQ + 4);

        float acc[4][4];
        #pragma unroll
        for (int t = 0; t < 4; t++)
            #pragma unroll
            for (int e = 0; e < 4; e++) acc[t][e] = 0.f;

        #pragma unroll
        for (int kg = 0; kg < 4; kg++) {
            #pragma unroll
            for (int t = 0; t < 4; t++) {
                uint4 B = *(const uint4*)(w1f + (size_t)((c * 4 + kg) * 8 + t) * 128);
                mma_f16(acc[t], af[2 * kg][0], af[2 * kg][1], af[2 * kg][2], af[2 * kg][3], B.x, B.y);
                mma_f16(acc[t], af[2 * kg + 1][0], af[2 * kg + 1][1], af[2 * kg + 1][2], af[2 * kg + 1][3], B.z, B.w);
            }
        }
        const float csv[8] = {csa.x, csa.y, csa.z, csa.w, csb.x, csb.y, csb.z, csb.w};
        const float gav[8] = {ga0.x, ga0.y, ga0.z, ga0.w, ga1.x, ga1.y, ga1.z, ga1.w};
        const float gbv[8] = {gb0.x, gb0.y, gb0.z, gb0.w, gb1.x, gb1.y, gb1.z, gb1.w};
        uint4 ua, ub;
        uint32_t* pu_a = &ua.x;
        uint32_t* pu_b = &ub.x;
        #pragma unroll
        for (int t = 0; t < 4; t++) {
            float p0v = ex2(fmaf(acc[t][0], L2E, fmaf(gav[2 * t],     HL2E, -csv[2 * t])));
            float p1v = ex2(fmaf(acc[t][1], L2E, fmaf(gav[2 * t + 1], HL2E, -csv[2 * t + 1])));
            float p2v = ex2(fmaf(acc[t][2], L2E, fmaf(gbv[2 * t],     HL2E, -csv[2 * t])));
            float p3v = ex2(fmaf(acc[t][3], L2E, fmaf(gbv[2 * t + 1], HL2E, -csv[2 * t + 1])));
            rs0 += p0v + p1v;
            rs1 += p2v + p3v;
            pu_a[t] = pk(p0v, p1v);
            pu_b[t] = pk(p2v, p3v);
        }
        const int wbase = (m0 + lg) * PSW + c * 32 + wq * 16 + 4 * lt;
        *(uint4*)(sP + wbase)           = ua;
        *(uint4*)(sP + wbase + 8 * PSW) = ub;
    }
    // rowsum partials ------------------------------------------------------
    rs0 += __shfl_xor_sync(0xffffffffu, rs0, 1);
    rs0 += __shfl_xor_sync(0xffffffffu, rs0, 2);
    rs1 += __shfl_xor_sync(0xffffffffu, rs1, 1);
    rs1 += __shfl_xor_sync(0xffffffffu, rs1, 2);
    if (lt == 0) {
        atomicAdd(&sRs[m0 + lg], rs0);
        atomicAdd(&sRs[m0 + lg + 8], rs1);
    }
    __syncthreads();                                // sP complete (cross-warp reads next)

    // ---------------- GEMM2: 32 rows x 32 d per warp -----------------------
    float qa[2][4][4];
    #pragma unroll
    for (int mt = 0; mt < 2; mt++)
        #pragma unroll
        for (int t = 0; t < 4; t++)
            #pragma unroll
            for (int e = 0; e < 4; e++) qa[mt][t][e] = 0.f;

    for (int c = 0; c < 8; c++) {
        #pragma unroll
        for (int g2 = 0; g2 < 2; g2++) {
            const int abase = (c * 2 + g2) * 16 + 4 * lt;
            uint4 U0 = *(const uint4*)(sP + (M2 + lg) * PSW + abase);
            uint4 U1 = *(const uint4*)(sP + (M2 + lg + 8) * PSW + abase);
            uint4 U2 = *(const uint4*)(sP + (M2 + lg + 16) * PSW + abase);
            uint4 U3 = *(const uint4*)(sP + (M2 + lg + 24) * PSW + abase);
            #pragma unroll
            for (int t = 0; t < 4; t++) {
                uint4 B = *(const uint4*)(wtf + (size_t)((c * 2 + g2) * 16 + t) * 128);
                mma_f16(qa[0][t], U0.x, U1.x, U0.y, U1.y, B.x, B.y);
                mma_f16(qa[0][t], U0.z, U1.z, U0.w, U1.w, B.z, B.w);
                mma_f16(qa[1][t], U2.x, U3.x, U2.y, U3.y, B.x, B.y);
                mma_f16(qa[1][t], U2.z, U3.z, U2.w, U3.w, B.z, B.w);
            }
        }
    }
    __syncthreads();                                // rowsum atomics visible
    if (tid < TM) sRinv[tid] = 1.0f / sRs[tid];
    __syncthreads();

    // avg_probs: thread tid owns codes (2*tid, 2*tid+1) ---------------------
    {
        float s0 = 0.f, s1 = 0.f;
        #pragma unroll 8
        for (int r = 0; r < TM; r++) {
            uint32_t u = sP[r * PSW + tid];
            __half2 h = *reinterpret_cast<__half2*>(&u);
            float2 f = __half22float2(h);
            float ri = sRinv[r];
            s0 = fmaf(f.x, ri, s0);
            s1 = fmaf(f.y, ri, s1);
        }
        atomicAdd(&g_avg[g * KQ + 2 * tid], s0);
        atomicAdd(&g_avg[g * KQ + 2 * tid + 1], s1);
    }
    __syncthreads();                                // sP free for staging

    // epilogue: normalize, single staging pass, coalesced STG.128 -----------
    {
        float* stage = (float*)(smc + OFF_P);       // [128 d][SXS]
        float rv[2][2];
        #pragma unroll
        for (int mt = 0; mt < 2; mt++) {
            rv[mt][0] = sRinv[M2 + mt * 16 + lg];
            rv[mt][1] = sRinv[M2 + mt * 16 + lg + 8];
        }
        #pragma unroll
        for (int mt = 0; mt < 2; mt++) {
            #pragma unroll
            for (int t = 0; t < 4; t++) {
                int d = wq2 * 32 + t * 8 + 2 * lt;
                int m = M2 + mt * 16 + lg;
                stage[d * SXS + m]           = qa[mt][t][0] * rv[mt][0];
                stage[(d + 1) * SXS + m]     = qa[mt][t][1] * rv[mt][0];
                stage[d * SXS + m + 8]       = qa[mt][t][2] * rv[mt][1];
                stage[(d + 1) * SXS + m + 8] = qa[mt][t][3] * rv[mt][1];
            }
        }
        __syncthreads();
        float* ob = out + ((size_t)(b * 512 + g * SDQ)) * TQ + t0;
        #pragma unroll
        for (int j = 0; j < 8; j++) {
            int i = tid + NTHR * j;
            int d = i >> 4, mq = (i & 15) * 4;
            float4 v = *(const float4*)(stage + d * SXS + mq);
            *(float4*)(ob + (size_t)d * TQ + mq) = v;
        }
    }

    // ---------------- perp: last CTA reduces g_avg -------------------------
    if (do_perp) {
        __shared__ unsigned s_last;
        __shared__ float se[8];
        __threadfence();
        __syncthreads();
        if (tid == 0)
            s_last = (atomicAdd(&g_ctr, 1u) == gridDim.x * gridDim.y - 1u) ? 1u : 0u;
        __syncthreads();
        if (s_last) {
            int gg = tid >> 6;
            int tt = tid & 63;
            float acc = 0.f;
            #pragma unroll
            for (int j = 0; j < 8; j++) {
                float a = g_avg[gg * KQ + tt + 64 * j] * (1.0f / (float)NTOK);
                acc += a * logf(a + 1e-10f);
            }
            #pragma unroll
            for (int o = 16; o; o >>= 1) acc += __shfl_xor_sync(0xffffffffu, acc, o);
            if (lane == 0) se[wid] = acc;
            __syncthreads();
            if (tid == 0) {
                float p = 0.f;
                #pragma unroll
                for (int g2 = 0; g2 < NG; g2++) p += expf(-(se[2 * g2] + se[2 * g2 + 1]));
                out[QUANT_ELEMS] = p;
            }
        }
    }
}

// ---------------------------------------------------------------------------
extern "C" void kernel_launch(void* const* d_in, const int* in_sizes, int n_in,
                              void* d_out, int out_size) {
    const float* x   = (const float*)d_in[0];
    const float* w0  = (const float*)d_in[1];
    const float* w1  = (const float*)d_in[2];
    const float* w2  = (const float*)d_in[3];
    const float* w3  = (const float*)d_in[4];
    const float* gum = (const float*)d_in[5];
    float* out = (float*)d_out;

    cudaFuncSetAttribute(gsm4_prep_kernel,
                         cudaFuncAttributeMaxDynamicSharedMemorySize, 128 * 132 * 4);
    cudaFuncSetAttribute(gsm4_fused_kernel,
                         cudaFuncAttributeMaxDynamicSharedMemorySize, SMEM_BYTES);

    gsm4_prep_kernel<<<64, 256, 128 * 132 * 4>>>(w0, w1, w2, w3);

    dim3 grid(NTOK / TM, NG);
    int do_perp = (out_size > QUANT_ELEMS) ? 1 : 0;
    gsm4_fused_kernel<<<grid, NTHR, SMEM_BYTES>>>(x, gum, out, do_perp);
}